// round 1
// baseline (speedup 1.0000x reference)
#include <cuda_runtime.h>
#include <math.h>

// ---------------------------------------------------------------------------
// Problem constants
// ---------------------------------------------------------------------------
#define BB 4
#define SS 1024
#define DD 1024
#define HH 16
#define HDIM 64
#define FF 2048
#define HID 4096
#define TOK (BB*SS)          // 4096 tokens

// ---------------------------------------------------------------------------
// Scratch (__device__ globals; no allocation allowed)
// ---------------------------------------------------------------------------
__device__ float g_q   [TOK*DD];
__device__ float g_k   [TOK*DD];
__device__ float g_v   [TOK*DD];
__device__ float g_att [TOK*DD];
__device__ float g_o   [TOK*DD];
__device__ float g_h   [TOK*DD];
__device__ float g_feat[TOK*DD];
__device__ float g_feat2[TOK*DD];
__device__ float g_pool[TOK*DD];
__device__ float g_ff  [TOK*FF];
__device__ float g_ph  [TOK*HID];
__device__ float g_s   [TOK];
__device__ float g_sv  [TOK];
__device__ int   g_seg [TOK];
__device__ float g_maxseg[BB];

// ---------------------------------------------------------------------------
// Helpers
// ---------------------------------------------------------------------------
__device__ __forceinline__ float gelu_f(float x) {
    return 0.5f * x * (1.0f + erff(x * 0.70710678118654752440f));
}

// ---------------------------------------------------------------------------
// Generic SGEMM: C[M,N] = act(A[M,K] @ W[K,N] + bias[N])
// BM=BN=128, BK=16, 256 threads, 8x8 microtile (split 64+64)
// act: 0 = none, 1 = exact GELU
// ---------------------------------------------------------------------------
__global__ __launch_bounds__(256)
void gemm_kernel(const float* __restrict__ A, const float* __restrict__ W,
                 const float* __restrict__ bias, float* __restrict__ C,
                 int M, int N, int K, int act)
{
    __shared__ float As[16][128];
    __shared__ float Bs[16][128];
    const int tid = threadIdx.x;
    const int tx  = tid & 15;
    const int ty  = tid >> 4;
    const int row0 = blockIdx.y * 128;
    const int col0 = blockIdx.x * 128;

    float acc[8][8];
#pragma unroll
    for (int i = 0; i < 8; i++)
#pragma unroll
        for (int j = 0; j < 8; j++) acc[i][j] = 0.0f;

    const int ar = tid >> 1;          // 0..127 (A row within tile)
    const int ak = (tid & 1) * 8;     // 0 or 8 (A k within tile)
    const int bk = tid >> 4;          // 0..15  (B k within tile)
    const int bn = (tid & 15) * 4;    // 0..60  (B col within tile)

    for (int k0 = 0; k0 < K; k0 += 16) {
        float4 a0 = *(const float4*)(A + (size_t)(row0 + ar) * K + k0 + ak);
        float4 a1 = *(const float4*)(A + (size_t)(row0 + ar) * K + k0 + ak + 4);
        float4 b0 = *(const float4*)(W + (size_t)(k0 + bk) * N + col0 + bn);
        float4 b1 = *(const float4*)(W + (size_t)(k0 + bk) * N + col0 + bn + 64);
        As[ak + 0][ar] = a0.x; As[ak + 1][ar] = a0.y;
        As[ak + 2][ar] = a0.z; As[ak + 3][ar] = a0.w;
        As[ak + 4][ar] = a1.x; As[ak + 5][ar] = a1.y;
        As[ak + 6][ar] = a1.z; As[ak + 7][ar] = a1.w;
        *(float4*)&Bs[bk][bn]      = b0;
        *(float4*)&Bs[bk][bn + 64] = b1;
        __syncthreads();
#pragma unroll
        for (int kk = 0; kk < 16; kk++) {
            float4 a0v = *(const float4*)&As[kk][ty * 4];
            float4 a1v = *(const float4*)&As[kk][64 + ty * 4];
            float4 b0v = *(const float4*)&Bs[kk][tx * 4];
            float4 b1v = *(const float4*)&Bs[kk][64 + tx * 4];
            float ra[8] = {a0v.x, a0v.y, a0v.z, a0v.w, a1v.x, a1v.y, a1v.z, a1v.w};
            float rb[8] = {b0v.x, b0v.y, b0v.z, b0v.w, b1v.x, b1v.y, b1v.z, b1v.w};
#pragma unroll
            for (int i = 0; i < 8; i++)
#pragma unroll
                for (int j = 0; j < 8; j++)
                    acc[i][j] = fmaf(ra[i], rb[j], acc[i][j]);
        }
        __syncthreads();
    }

#pragma unroll
    for (int i = 0; i < 8; i++) {
        int r = row0 + ((i < 4) ? (ty * 4 + i) : (64 + ty * 4 + (i - 4)));
#pragma unroll
        for (int jb = 0; jb < 2; jb++) {
            int c = col0 + jb * 64 + tx * 4;
            float v0 = acc[i][jb * 4 + 0] + bias[c + 0];
            float v1 = acc[i][jb * 4 + 1] + bias[c + 1];
            float v2 = acc[i][jb * 4 + 2] + bias[c + 2];
            float v3 = acc[i][jb * 4 + 3] + bias[c + 3];
            if (act == 1) { v0 = gelu_f(v0); v1 = gelu_f(v1); v2 = gelu_f(v2); v3 = gelu_f(v3); }
            float4 out4 = make_float4(v0, v1, v2, v3);
            *(float4*)(C + (size_t)r * N + c) = out4;
        }
    }
}

// ---------------------------------------------------------------------------
// Flash attention: per (b,h) head, 64-query tile, loop over 16 key tiles.
// q,k,v,o layouts: [B,S,D] with head slice at offset h*64.
// mode 0: score += masks[b,key] (torch float key_padding_mask added)
// mode 1: score += (masks>0 ? 0 : -1e9)
// ---------------------------------------------------------------------------
__global__ __launch_bounds__(256)
void attn_kernel(const float* __restrict__ q, const float* __restrict__ k,
                 const float* __restrict__ v, const float* __restrict__ masks,
                 int mode, float* __restrict__ o)
{
    __shared__ float Qt[64][64];   // [d][q]
    __shared__ float KP[64][64];   // K as [d][k], later P as [k][q]
    __shared__ float Vs[64][64];   // [k][d]

    const int tid = threadIdx.x;
    const int tx  = tid & 15;
    const int ty  = tid >> 4;
    const int q0  = blockIdx.x * 64;
    const int bh  = blockIdx.y;
    const int b   = bh >> 4;
    const int h   = bh & 15;
    const size_t base = (size_t)b * SS * DD + (size_t)h * HDIM;

    for (int idx = tid; idx < 4096; idx += 256) {
        int qq = idx >> 6, d = idx & 63;
        Qt[d][qq] = q[base + (size_t)(q0 + qq) * DD + d];
    }

    float mrow[4], lrow[4], Oacc[4][4];
#pragma unroll
    for (int i = 0; i < 4; i++) {
        mrow[i] = -1e30f; lrow[i] = 0.0f;
#pragma unroll
        for (int j = 0; j < 4; j++) Oacc[i][j] = 0.0f;
    }
    __syncthreads();

    for (int t = 0; t < 16; t++) {
        const int k0 = t * 64;
        // load K (transposed) and V
        for (int idx = tid; idx < 4096; idx += 256) {
            int kk = idx >> 6, d = idx & 63;
            KP[d][kk] = k[base + (size_t)(k0 + kk) * DD + d];
            Vs[kk][d] = v[base + (size_t)(k0 + kk) * DD + d];
        }
        __syncthreads();

        // scores S[4q][4k]
        float S[4][4];
#pragma unroll
        for (int i = 0; i < 4; i++)
#pragma unroll
            for (int j = 0; j < 4; j++) S[i][j] = 0.0f;
#pragma unroll
        for (int d = 0; d < 64; d++) {
            float4 qa = *(const float4*)&Qt[d][ty * 4];
            float4 kb = *(const float4*)&KP[d][tx * 4];
            float ra[4] = {qa.x, qa.y, qa.z, qa.w};
            float rb[4] = {kb.x, kb.y, kb.z, kb.w};
#pragma unroll
            for (int i = 0; i < 4; i++)
#pragma unroll
                for (int j = 0; j < 4; j++)
                    S[i][j] = fmaf(ra[i], rb[j], S[i][j]);
        }
        // bias + scale
        float bia[4];
#pragma unroll
        for (int j = 0; j < 4; j++) {
            float mv = masks[b * SS + k0 + tx * 4 + j];
            bia[j] = (mode == 0) ? mv : (mv > 0.0f ? 0.0f : -1e9f);
        }
#pragma unroll
        for (int i = 0; i < 4; i++)
#pragma unroll
            for (int j = 0; j < 4; j++)
                S[i][j] = S[i][j] * 0.125f + bia[j];

        // row max (butterfly over the 16-lane tx group)
        float tmax[4];
#pragma unroll
        for (int i = 0; i < 4; i++) {
            float mx = fmaxf(fmaxf(S[i][0], S[i][1]), fmaxf(S[i][2], S[i][3]));
#pragma unroll
            for (int sh = 1; sh < 16; sh <<= 1)
                mx = fmaxf(mx, __shfl_xor_sync(0xffffffffu, mx, sh));
            tmax[i] = mx;
        }
        float mnew[4], scl[4], rsum[4];
#pragma unroll
        for (int i = 0; i < 4; i++) {
            mnew[i] = fmaxf(mrow[i], tmax[i]);
            scl[i]  = __expf(mrow[i] - mnew[i]);
            rsum[i] = 0.0f;
        }
#pragma unroll
        for (int i = 0; i < 4; i++)
#pragma unroll
            for (int j = 0; j < 4; j++) {
                float p = __expf(S[i][j] - mnew[i]);
                S[i][j] = p;
                rsum[i] += p;
            }
#pragma unroll
        for (int i = 0; i < 4; i++) {
#pragma unroll
            for (int sh = 1; sh < 16; sh <<= 1)
                rsum[i] += __shfl_xor_sync(0xffffffffu, rsum[i], sh);
            lrow[i] = lrow[i] * scl[i] + rsum[i];
            mrow[i] = mnew[i];
#pragma unroll
            for (int j = 0; j < 4; j++) Oacc[i][j] *= scl[i];
        }
        __syncthreads();   // all K reads done, safe to overwrite KP with P
#pragma unroll
        for (int i = 0; i < 4; i++)
#pragma unroll
            for (int j = 0; j < 4; j++)
                KP[tx * 4 + j][ty * 4 + i] = S[i][j];
        __syncthreads();
        // O += P @ V
#pragma unroll
        for (int kk = 0; kk < 64; kk++) {
            float4 pa = *(const float4*)&KP[kk][ty * 4];
            float4 vb = *(const float4*)&Vs[kk][tx * 4];
            float ra[4] = {pa.x, pa.y, pa.z, pa.w};
            float rb[4] = {vb.x, vb.y, vb.z, vb.w};
#pragma unroll
            for (int i = 0; i < 4; i++)
#pragma unroll
                for (int j = 0; j < 4; j++)
                    Oacc[i][j] = fmaf(ra[i], rb[j], Oacc[i][j]);
        }
        __syncthreads();   // PV reads done before next tile overwrites KP/Vs
    }

#pragma unroll
    for (int i = 0; i < 4; i++) {
        float inv = 1.0f / lrow[i];
        float4 ov = make_float4(Oacc[i][0] * inv, Oacc[i][1] * inv,
                                Oacc[i][2] * inv, Oacc[i][3] * inv);
        *(float4*)(o + base + (size_t)(q0 + ty * 4 + i) * DD + tx * 4) = ov;
    }
}

// ---------------------------------------------------------------------------
// out = LayerNorm(a + b) * g + beta ; one block per token row, D=1024
// ---------------------------------------------------------------------------
__global__ __launch_bounds__(256)
void add_ln_kernel(const float* __restrict__ a, const float* __restrict__ b2,
                   const float* __restrict__ g, const float* __restrict__ beta,
                   float* __restrict__ out)
{
    const int row = blockIdx.x;
    const size_t off = (size_t)row * DD;
    const int t = threadIdx.x;
    __shared__ float r1[256], r2[256];

    float vloc[4];
    float s = 0.0f, s2 = 0.0f;
#pragma unroll
    for (int i = 0; i < 4; i++) {
        int d = t + i * 256;
        float vv = a[off + d] + b2[off + d];
        vloc[i] = vv;
        s += vv; s2 += vv * vv;
    }
    r1[t] = s; r2[t] = s2;
    __syncthreads();
    for (int o2 = 128; o2 > 0; o2 >>= 1) {
        if (t < o2) { r1[t] += r1[t + o2]; r2[t] += r2[t + o2]; }
        __syncthreads();
    }
    float mean = r1[0] * (1.0f / DD);
    float var  = r2[0] * (1.0f / DD) - mean * mean;
    float inv  = rsqrtf(var + 1e-5f);
#pragma unroll
    for (int i = 0; i < 4; i++) {
        int d = t + i * 256;
        out[off + d] = (vloc[i] - mean) * inv * g[d] + beta[d];
    }
}

// ---------------------------------------------------------------------------
// s = sigmoid(feat @ Ws + bs); one warp per token
// ---------------------------------------------------------------------------
__global__ __launch_bounds__(256)
void score_kernel(const float* __restrict__ feat, const float* __restrict__ Ws,
                  const float* __restrict__ bs, float* __restrict__ sbuf)
{
    int token = blockIdx.x * 8 + (threadIdx.x >> 5);
    int lane  = threadIdx.x & 31;
    const float* f = feat + (size_t)token * DD;
    float acc = 0.0f;
    for (int i = lane; i < DD; i += 32) acc += f[i] * Ws[i];
#pragma unroll
    for (int m = 16; m; m >>= 1) acc += __shfl_xor_sync(0xffffffffu, acc, m);
    if (lane == 0) sbuf[token] = 1.0f / (1.0f + expf(-(acc + bs[0])));
}

// ---------------------------------------------------------------------------
// Per-batch inclusive scan of sv, floor -> segment ids, max over valid
// ---------------------------------------------------------------------------
__global__ __launch_bounds__(1024)
void scan_kernel(const float* __restrict__ sbuf, const float* __restrict__ masks,
                 float* __restrict__ svbuf, int* __restrict__ segbuf,
                 float* __restrict__ maxseg)
{
    const int b = blockIdx.x;
    const int t = threadIdx.x;
    __shared__ float sc[SS];
    __shared__ float mr[SS];

    float valid = masks[b * SS + t];
    float sv = (valid > 0.0f) ? sbuf[b * SS + t] : 0.0f;
    svbuf[b * SS + t] = sv;
    sc[t] = sv;
    __syncthreads();
    for (int off = 1; off < SS; off <<= 1) {
        float vprev = (t >= off) ? sc[t - off] : 0.0f;
        __syncthreads();
        sc[t] += vprev;
        __syncthreads();
    }
    float c = floorf(sc[t]);
    int seg = (int)c;
    seg = seg < 0 ? 0 : (seg > SS - 1 ? SS - 1 : seg);
    segbuf[b * SS + t] = seg;

    mr[t] = (valid > 0.0f) ? c : -1.0f;
    __syncthreads();
    for (int off = 512; off > 0; off >>= 1) {
        if (t < off) mr[t] = fmaxf(mr[t], mr[t + off]);
        __syncthreads();
    }
    if (t == 0) maxseg[b] = mr[0];
}

// ---------------------------------------------------------------------------
// pooled[b,g,:] = sum_{s: seg[b,s]==g} x[b,s,:]*sv[b,s]
// seg is nondecreasing -> binary search the token range (deterministic)
// ---------------------------------------------------------------------------
__global__ __launch_bounds__(256)
void pool_kernel(const float* __restrict__ x, const float* __restrict__ svbuf,
                 const int* __restrict__ segbuf, float* __restrict__ pooled)
{
    const int g = blockIdx.x;
    const int b = blockIdx.y;
    const int* seg = segbuf + b * SS;

    // lower_bound(g)
    int lo = 0, hi = SS;
    while (lo < hi) { int mid = (lo + hi) >> 1; if (seg[mid] < g) lo = mid + 1; else hi = mid; }
    int beg = lo;
    // lower_bound(g+1)
    lo = beg; hi = SS;
    while (lo < hi) { int mid = (lo + hi) >> 1; if (seg[mid] < g + 1) lo = mid + 1; else hi = mid; }
    int end = lo;

    const int t = threadIdx.x;
    float acc[4] = {0.0f, 0.0f, 0.0f, 0.0f};
    for (int s = beg; s < end; s++) {
        float w = svbuf[b * SS + s];
        const float* xr = x + ((size_t)b * SS + s) * DD;
#pragma unroll
        for (int i = 0; i < 4; i++) acc[i] += xr[t + i * 256] * w;
    }
    float* pr = pooled + ((size_t)b * SS + g) * DD;
#pragma unroll
    for (int i = 0; i < 4; i++) pr[t + i * 256] = acc[i];
}

// ---------------------------------------------------------------------------
// new_mask[b,s] = (s <= max_seg[b]) ? 1 : 0
// ---------------------------------------------------------------------------
__global__ __launch_bounds__(1024)
void mask_kernel(const float* __restrict__ maxseg, float* __restrict__ outmask)
{
    const int b = blockIdx.x;
    const int t = threadIdx.x;
    outmask[b * SS + t] = ((float)t <= maxseg[b]) ? 1.0f : 0.0f;
}

// ---------------------------------------------------------------------------
// Host side
// ---------------------------------------------------------------------------
static float* sym_addr_f(const void* sym) {
    void* p = nullptr;
    cudaGetSymbolAddress(&p, sym);
    return (float*)p;
}

static void launch_gemm(const float* A, const float* W, const float* bias,
                        float* C, int M, int N, int K, int act) {
    dim3 grid(N / 128, M / 128);
    gemm_kernel<<<grid, 256>>>(A, W, bias, C, M, N, K, act);
}

extern "C" void kernel_launch(void* const* d_in, const int* in_sizes, int n_in,
                              void* d_out, int out_size)
{
    (void)in_sizes; (void)n_in;
    const float* x     = (const float*)d_in[0];
    const float* masks = (const float*)d_in[1];
    const float* Wq  = (const float*)d_in[2];
    const float* bq  = (const float*)d_in[3];
    const float* Wk  = (const float*)d_in[4];
    const float* bk  = (const float*)d_in[5];
    const float* Wv  = (const float*)d_in[6];
    const float* bv  = (const float*)d_in[7];
    const float* Wo  = (const float*)d_in[8];
    const float* bo  = (const float*)d_in[9];
    const float* g1  = (const float*)d_in[10];
    const float* be1 = (const float*)d_in[11];
    const float* g2  = (const float*)d_in[12];
    const float* be2 = (const float*)d_in[13];
    const float* W1  = (const float*)d_in[14];
    const float* bf1 = (const float*)d_in[15];
    const float* W2  = (const float*)d_in[16];
    const float* bf2 = (const float*)d_in[17];
    const float* Ws  = (const float*)d_in[18];
    const float* bs  = (const float*)d_in[19];
    const float* P1  = (const float*)d_in[20];
    const float* bp1 = (const float*)d_in[21];
    const float* P2  = (const float*)d_in[22];
    const float* bp2 = (const float*)d_in[23];

    float* out = (float*)d_out;
    (void)out_size;

    float* qb    = sym_addr_f(g_q);
    float* kb2   = sym_addr_f(g_k);
    float* vb2   = sym_addr_f(g_v);
    float* attb  = sym_addr_f(g_att);
    float* ob    = sym_addr_f(g_o);
    float* hb    = sym_addr_f(g_h);
    float* featb = sym_addr_f(g_feat);
    float* feat2b= sym_addr_f(g_feat2);
    float* poolb = sym_addr_f(g_pool);
    float* ffb   = sym_addr_f(g_ff);
    float* phb   = sym_addr_f(g_ph);
    float* sb    = sym_addr_f(g_s);
    float* svb   = sym_addr_f(g_sv);
    int*   segb  = (int*)sym_addr_f(g_seg);
    float* msb   = sym_addr_f(g_maxseg);

    // ---- encoder layer, applied twice ----
    const float* enc_in = x;
    float* enc_out = featb;
    for (int pass = 0; pass < 2; pass++) {
        int mode = pass;  // pass 0: add masks float bias; pass 1: 0 / -1e9
        launch_gemm(enc_in, Wq, bq, qb,  TOK, DD, DD, 0);
        launch_gemm(enc_in, Wk, bk, kb2, TOK, DD, DD, 0);
        launch_gemm(enc_in, Wv, bv, vb2, TOK, DD, DD, 0);
        attn_kernel<<<dim3(SS / 64, BB * HH), 256>>>(qb, kb2, vb2, masks, mode, attb);
        launch_gemm(attb, Wo, bo, ob, TOK, DD, DD, 0);
        add_ln_kernel<<<TOK, 256>>>(enc_in, ob, g1, be1, hb);
        launch_gemm(hb, W1, bf1, ffb, TOK, FF, DD, 1);   // GELU
        launch_gemm(ffb, W2, bf2, ob, TOK, DD, FF, 0);
        add_ln_kernel<<<TOK, 256>>>(hb, ob, g2, be2, enc_out);
        enc_in = featb;
        enc_out = feat2b;
    }

    // ---- importance scores, cumsum segmentation ----
    score_kernel<<<TOK / 8, 256>>>(feat2b, Ws, bs, sb);
    scan_kernel<<<BB, 1024>>>(sb, masks, svb, segb, msb);

    // ---- weighted segment-sum pooling of original x ----
    pool_kernel<<<dim3(SS, BB), 256>>>(x, svb, segb, poolb);

    // ---- projector: gelu(pooled@P1+bp1)@P2+bp2 -> out ----
    launch_gemm(poolb, P1, bp1, phb, TOK, HID, DD, 1);   // GELU
    launch_gemm(phb, P2, bp2, out, TOK, HID, HID, 0);

    // ---- new_mask appended after the [B,S,HID] output ----
    mask_kernel<<<BB, 1024>>>(msb, out + (size_t)TOK * HID);
}

// round 3
// speedup vs baseline: 1.2935x; 1.2935x over previous
#include <cuda_runtime.h>
#include <cstdint>
#include <math.h>

// ---------------------------------------------------------------------------
// Problem constants
// ---------------------------------------------------------------------------
#define BB 4
#define SS 1024
#define DD 1024
#define HH 16
#define HDIM 64
#define FF 2048
#define HID 4096
#define TOK (BB*SS)          // 4096 tokens

// ---------------------------------------------------------------------------
// Scratch (__device__ globals; no allocation allowed)
// ---------------------------------------------------------------------------
__device__ float g_q   [TOK*DD];
__device__ float g_k   [TOK*DD];
__device__ float g_v   [TOK*DD];
__device__ float g_att [TOK*DD];
__device__ float g_o   [TOK*DD];
__device__ float g_h   [TOK*DD];
__device__ float g_feat[TOK*DD];
__device__ float g_feat2[TOK*DD];
__device__ float g_pool[TOK*DD];
__device__ float g_ff  [TOK*FF];
__device__ float g_ph  [TOK*HID];
__device__ float g_s   [TOK];
__device__ float g_sv  [TOK];
__device__ int   g_seg [TOK];
__device__ float g_maxseg[BB];

// transposed weights [N,K] row-major (K contiguous) for the mma B operand
__device__ float g_wt_q [DD*DD];
__device__ float g_wt_k [DD*DD];
__device__ float g_wt_v [DD*DD];
__device__ float g_wt_o [DD*DD];
__device__ float g_wt_1 [FF*DD];    // W1^T: [2048,1024]
__device__ float g_wt_2 [DD*FF];    // W2^T: [1024,2048]
__device__ float g_wt_p1[HID*DD];   // P1^T: [4096,1024]
__device__ float g_wt_p2[HID*HID];  // P2^T: [4096,4096]

// ---------------------------------------------------------------------------
// Helpers
// ---------------------------------------------------------------------------
__device__ __forceinline__ float gelu_f(float x) {
    return 0.5f * x * (1.0f + erff(x * 0.70710678118654752440f));
}

__device__ __forceinline__ void cp16(uint32_t dst, const void* src) {
    asm volatile("cp.async.cg.shared.global [%0], [%1], 16;\n"
                 :: "r"(dst), "l"(src));
}

__device__ __forceinline__ uint32_t smem_u32(const void* p) {
    uint32_t a;
    asm("{ .reg .u64 t; cvta.to.shared.u64 t, %1; cvt.u32.u64 %0, t; }"
        : "=r"(a) : "l"(p));
    return a;
}

// mma.sync m16n8k8 tf32: D += A*B (C=D accumulate in-place)
__device__ __forceinline__ void mma_tf32(float* c,
                                         uint32_t a0, uint32_t a1,
                                         uint32_t a2, uint32_t a3,
                                         uint32_t b0, uint32_t b1) {
    asm volatile(
        "mma.sync.aligned.m16n8k8.row.col.f32.tf32.tf32.f32 "
        "{%0,%1,%2,%3}, {%4,%5,%6,%7}, {%8,%9}, {%0,%1,%2,%3};\n"
        : "+f"(c[0]), "+f"(c[1]), "+f"(c[2]), "+f"(c[3])
        : "r"(a0), "r"(a1), "r"(a2), "r"(a3), "r"(b0), "r"(b1));
}

// ---------------------------------------------------------------------------
// tf32 tensor-core GEMM with exact 2-way split (fp32-equivalent accuracy)
// C[M,N] = act(A[M,K] @ Bt[N,K]^T + bias[N])
// BM=BN=128, BK=16, 256 threads. Warp tile 32x64 (warp grid 4m x 2n).
// smem rows padded to 20 floats -> conflict-free fragment LDS.
// ---------------------------------------------------------------------------
#define PAD 20

__global__ __launch_bounds__(256)
void mma_gemm_kernel(const float* __restrict__ A, const float* __restrict__ Bt,
                     const float* __restrict__ bias, float* __restrict__ C,
                     int M, int N, int K, int act)
{
    __shared__ float As[2][128 * PAD];
    __shared__ float Bs[2][128 * PAD];

    const int tid  = threadIdx.x;
    const int wid  = tid >> 5;
    const int lane = tid & 31;
    const int gr   = lane >> 2;     // 0..7
    const int gc   = lane & 3;      // 0..3
    const int row0 = blockIdx.y * 128;
    const int col0 = blockIdx.x * 128;
    const int warp_m = (wid & 3) * 32;
    const int warp_n = (wid >> 2) * 64;

    const uint32_t sA = smem_u32(&As[0][0]);
    const uint32_t sB = smem_u32(&Bs[0][0]);

    float acc[2][8][4];
#pragma unroll
    for (int i = 0; i < 2; i++)
#pragma unroll
        for (int j = 0; j < 8; j++)
#pragma unroll
            for (int r = 0; r < 4; r++) acc[i][j][r] = 0.0f;

    const int nk = K >> 4;

    // chunk assignment: chunk = tid + 256*j ; m = chunk>>2 ; kc = (chunk&3)*4
    const int m_a  = tid >> 2;
    const int kc_a = (tid & 3) << 2;

    // prologue: load tile 0
    {
        const int k0 = 0;
#pragma unroll
        for (int j = 0; j < 2; j++) {
            int m = m_a + j * 64;
            cp16(sA + (uint32_t)(m * PAD + kc_a) * 4u,
                 A + (size_t)(row0 + m) * K + k0 + kc_a);
            cp16(sB + (uint32_t)(m * PAD + kc_a) * 4u,
                 Bt + (size_t)(col0 + m) * K + k0 + kc_a);
        }
        asm volatile("cp.async.commit_group;\n");
    }

    for (int t = 0; t < nk; t++) {
        const int st = t & 1;
        if (t + 1 < nk) {
            const int st2 = (t + 1) & 1;
            const int k0 = (t + 1) << 4;
#pragma unroll
            for (int j = 0; j < 2; j++) {
                int m = m_a + j * 64;
                cp16(sA + (uint32_t)(st2 * 128 * PAD + m * PAD + kc_a) * 4u,
                     A + (size_t)(row0 + m) * K + k0 + kc_a);
                cp16(sB + (uint32_t)(st2 * 128 * PAD + m * PAD + kc_a) * 4u,
                     Bt + (size_t)(col0 + m) * K + k0 + kc_a);
            }
            asm volatile("cp.async.commit_group;\n");
            asm volatile("cp.async.wait_group 1;\n");
        } else {
            asm volatile("cp.async.wait_group 0;\n");
        }
        __syncthreads();

        const float* as = &As[st][0];
        const float* bs = &Bs[st][0];

#pragma unroll
        for (int k8 = 0; k8 < 16; k8 += 8) {
            // ---- load + split A fragments (2 m-tiles)
            uint32_t ah[2][4], al[2][4];
#pragma unroll
            for (int mt = 0; mt < 2; mt++) {
                int base = (warp_m + mt * 16 + gr) * PAD + k8 + gc;
                float v0 = as[base];
                float v1 = as[base + 8 * PAD];
                float v2 = as[base + 4];
                float v3 = as[base + 8 * PAD + 4];
                uint32_t h0 = __float_as_uint(v0) & 0xFFFFE000u;
                uint32_t h1 = __float_as_uint(v1) & 0xFFFFE000u;
                uint32_t h2 = __float_as_uint(v2) & 0xFFFFE000u;
                uint32_t h3 = __float_as_uint(v3) & 0xFFFFE000u;
                ah[mt][0] = h0; ah[mt][1] = h1; ah[mt][2] = h2; ah[mt][3] = h3;
                al[mt][0] = __float_as_uint(v0 - __uint_as_float(h0));
                al[mt][1] = __float_as_uint(v1 - __uint_as_float(h1));
                al[mt][2] = __float_as_uint(v2 - __uint_as_float(h2));
                al[mt][3] = __float_as_uint(v3 - __uint_as_float(h3));
            }
            // ---- load + split B fragments (8 n-tiles)
            uint32_t bh[8][2], bl[8][2];
#pragma unroll
            for (int nt = 0; nt < 8; nt++) {
                int base = (warp_n + nt * 8 + gr) * PAD + k8 + gc;
                float v0 = bs[base];
                float v1 = bs[base + 4];
                uint32_t h0 = __float_as_uint(v0) & 0xFFFFE000u;
                uint32_t h1 = __float_as_uint(v1) & 0xFFFFE000u;
                bh[nt][0] = h0; bh[nt][1] = h1;
                bl[nt][0] = __float_as_uint(v0 - __uint_as_float(h0));
                bl[nt][1] = __float_as_uint(v1 - __uint_as_float(h1));
            }
            // ---- 16 tiles x 3 combos
#pragma unroll
            for (int mt = 0; mt < 2; mt++)
#pragma unroll
                for (int nt = 0; nt < 8; nt++) {
                    float* c = acc[mt][nt];
                    mma_tf32(c, ah[mt][0], ah[mt][1], ah[mt][2], ah[mt][3],
                             bh[nt][0], bh[nt][1]);
                    mma_tf32(c, ah[mt][0], ah[mt][1], ah[mt][2], ah[mt][3],
                             bl[nt][0], bl[nt][1]);
                    mma_tf32(c, al[mt][0], al[mt][1], al[mt][2], al[mt][3],
                             bh[nt][0], bh[nt][1]);
                }
        }
        __syncthreads();
    }

    // ---- epilogue
#pragma unroll
    for (int mt = 0; mt < 2; mt++) {
        const int r0 = row0 + warp_m + mt * 16 + gr;
#pragma unroll
        for (int nt = 0; nt < 8; nt++) {
            const int cc = col0 + warp_n + nt * 8 + 2 * gc;
            float b0v = bias[cc], b1v = bias[cc + 1];
            float v0 = acc[mt][nt][0] + b0v;
            float v1 = acc[mt][nt][1] + b1v;
            float v2 = acc[mt][nt][2] + b0v;
            float v3 = acc[mt][nt][3] + b1v;
            if (act == 1) {
                v0 = gelu_f(v0); v1 = gelu_f(v1);
                v2 = gelu_f(v2); v3 = gelu_f(v3);
            }
            *(float2*)(C + (size_t)r0 * N + cc)       = make_float2(v0, v1);
            *(float2*)(C + (size_t)(r0 + 8) * N + cc) = make_float2(v2, v3);
        }
    }
}

// ---------------------------------------------------------------------------
// Weight transpose: Wt[n,k] = W[k,n]
// ---------------------------------------------------------------------------
__global__ __launch_bounds__(256)
void transpose_kernel(const float* __restrict__ W, float* __restrict__ Wt,
                      int Kd, int Nd)
{
    __shared__ float t[32][33];
    const int n0 = blockIdx.x * 32, k0 = blockIdx.y * 32;
    const int tx = threadIdx.x & 31, ty = threadIdx.x >> 5;
#pragma unroll
    for (int r = ty; r < 32; r += 8)
        t[r][tx] = W[(size_t)(k0 + r) * Nd + n0 + tx];
    __syncthreads();
#pragma unroll
    for (int r = ty; r < 32; r += 8)
        Wt[(size_t)(n0 + r) * Kd + k0 + tx] = t[tx][r];
}

// ---------------------------------------------------------------------------
// Flash attention: per (b,h) head, 64-query tile, loop over 16 key tiles.
// mode 0: score += masks[b,key]; mode 1: score += (masks>0 ? 0 : -1e9)
// ---------------------------------------------------------------------------
__global__ __launch_bounds__(256)
void attn_kernel(const float* __restrict__ q, const float* __restrict__ k,
                 const float* __restrict__ v, const float* __restrict__ masks,
                 int mode, float* __restrict__ o)
{
    __shared__ float Qt[64][64];   // [d][q]
    __shared__ float KP[64][64];   // K as [d][k], later P as [k][q]
    __shared__ float Vs[64][64];   // [k][d]

    const int tid = threadIdx.x;
    const int tx  = tid & 15;
    const int ty  = tid >> 4;
    const int q0  = blockIdx.x * 64;
    const int bh  = blockIdx.y;
    const int b   = bh >> 4;
    const int h   = bh & 15;
    const size_t base = (size_t)b * SS * DD + (size_t)h * HDIM;

    for (int idx = tid; idx < 4096; idx += 256) {
        int qq = idx >> 6, d = idx & 63;
        Qt[d][qq] = q[base + (size_t)(q0 + qq) * DD + d];
    }

    float mrow[4], lrow[4], Oacc[4][4];
#pragma unroll
    for (int i = 0; i < 4; i++) {
        mrow[i] = -1e30f; lrow[i] = 0.0f;
#pragma unroll
        for (int j = 0; j < 4; j++) Oacc[i][j] = 0.0f;
    }
    __syncthreads();

    for (int t = 0; t < 16; t++) {
        const int k0 = t * 64;
        for (int idx = tid; idx < 4096; idx += 256) {
            int kk = idx >> 6, d = idx & 63;
            KP[d][kk] = k[base + (size_t)(k0 + kk) * DD + d];
            Vs[kk][d] = v[base + (size_t)(k0 + kk) * DD + d];
        }
        __syncthreads();

        float S[4][4];
#pragma unroll
        for (int i = 0; i < 4; i++)
#pragma unroll
            for (int j = 0; j < 4; j++) S[i][j] = 0.0f;
#pragma unroll
        for (int d = 0; d < 64; d++) {
            float4 qa = *(const float4*)&Qt[d][ty * 4];
            float4 kb = *(const float4*)&KP[d][tx * 4];
            float ra[4] = {qa.x, qa.y, qa.z, qa.w};
            float rb[4] = {kb.x, kb.y, kb.z, kb.w};
#pragma unroll
            for (int i = 0; i < 4; i++)
#pragma unroll
                for (int j = 0; j < 4; j++)
                    S[i][j] = fmaf(ra[i], rb[j], S[i][j]);
        }
        float bia[4];
#pragma unroll
        for (int j = 0; j < 4; j++) {
            float mv = masks[b * SS + k0 + tx * 4 + j];
            bia[j] = (mode == 0) ? mv : (mv > 0.0f ? 0.0f : -1e9f);
        }
#pragma unroll
        for (int i = 0; i < 4; i++)
#pragma unroll
            for (int j = 0; j < 4; j++)
                S[i][j] = S[i][j] * 0.125f + bia[j];

        float tmax[4];
#pragma unroll
        for (int i = 0; i < 4; i++) {
            float mx = fmaxf(fmaxf(S[i][0], S[i][1]), fmaxf(S[i][2], S[i][3]));
#pragma unroll
            for (int sh = 1; sh < 16; sh <<= 1)
                mx = fmaxf(mx, __shfl_xor_sync(0xffffffffu, mx, sh));
            tmax[i] = mx;
        }
        float mnew[4], scl[4], rsum[4];
#pragma unroll
        for (int i = 0; i < 4; i++) {
            mnew[i] = fmaxf(mrow[i], tmax[i]);
            scl[i]  = __expf(mrow[i] - mnew[i]);
            rsum[i] = 0.0f;
        }
#pragma unroll
        for (int i = 0; i < 4; i++)
#pragma unroll
            for (int j = 0; j < 4; j++) {
                float p = __expf(S[i][j] - mnew[i]);
                S[i][j] = p;
                rsum[i] += p;
            }
#pragma unroll
        for (int i = 0; i < 4; i++) {
#pragma unroll
            for (int sh = 1; sh < 16; sh <<= 1)
                rsum[i] += __shfl_xor_sync(0xffffffffu, rsum[i], sh);
            lrow[i] = lrow[i] * scl[i] + rsum[i];
            mrow[i] = mnew[i];
#pragma unroll
            for (int j = 0; j < 4; j++) Oacc[i][j] *= scl[i];
        }
        __syncthreads();
#pragma unroll
        for (int i = 0; i < 4; i++)
#pragma unroll
            for (int j = 0; j < 4; j++)
                KP[tx * 4 + j][ty * 4 + i] = S[i][j];
        __syncthreads();
#pragma unroll
        for (int kk = 0; kk < 64; kk++) {
            float4 pa = *(const float4*)&KP[kk][ty * 4];
            float4 vb = *(const float4*)&Vs[kk][tx * 4];
            float ra[4] = {pa.x, pa.y, pa.z, pa.w};
            float rb[4] = {vb.x, vb.y, vb.z, vb.w};
#pragma unroll
            for (int i = 0; i < 4; i++)
#pragma unroll
                for (int j = 0; j < 4; j++)
                    Oacc[i][j] = fmaf(ra[i], rb[j], Oacc[i][j]);
        }
        __syncthreads();
    }

#pragma unroll
    for (int i = 0; i < 4; i++) {
        float inv = 1.0f / lrow[i];
        float4 ov = make_float4(Oacc[i][0] * inv, Oacc[i][1] * inv,
                                Oacc[i][2] * inv, Oacc[i][3] * inv);
        *(float4*)(o + base + (size_t)(q0 + ty * 4 + i) * DD + tx * 4) = ov;
    }
}

// ---------------------------------------------------------------------------
// out = LayerNorm(a + b) * g + beta ; one block per token row, D=1024
// ---------------------------------------------------------------------------
__global__ __launch_bounds__(256)
void add_ln_kernel(const float* __restrict__ a, const float* __restrict__ b2,
                   const float* __restrict__ g, const float* __restrict__ beta,
                   float* __restrict__ out)
{
    const int row = blockIdx.x;
    const size_t off = (size_t)row * DD;
    const int t = threadIdx.x;
    __shared__ float r1[256], r2[256];

    float vloc[4];
    float s = 0.0f, s2 = 0.0f;
#pragma unroll
    for (int i = 0; i < 4; i++) {
        int d = t + i * 256;
        float vv = a[off + d] + b2[off + d];
        vloc[i] = vv;
        s += vv; s2 += vv * vv;
    }
    r1[t] = s; r2[t] = s2;
    __syncthreads();
    for (int o2 = 128; o2 > 0; o2 >>= 1) {
        if (t < o2) { r1[t] += r1[t + o2]; r2[t] += r2[t + o2]; }
        __syncthreads();
    }
    float mean = r1[0] * (1.0f / DD);
    float var  = r2[0] * (1.0f / DD) - mean * mean;
    float inv  = rsqrtf(var + 1e-5f);
#pragma unroll
    for (int i = 0; i < 4; i++) {
        int d = t + i * 256;
        out[off + d] = (vloc[i] - mean) * inv * g[d] + beta[d];
    }
}

// ---------------------------------------------------------------------------
// s = sigmoid(feat @ Ws + bs); one warp per token
// ---------------------------------------------------------------------------
__global__ __launch_bounds__(256)
void score_kernel(const float* __restrict__ feat, const float* __restrict__ Ws,
                  const float* __restrict__ bs, float* __restrict__ sbuf)
{
    int token = blockIdx.x * 8 + (threadIdx.x >> 5);
    int lane  = threadIdx.x & 31;
    const float* f = feat + (size_t)token * DD;
    float acc = 0.0f;
    for (int i = lane; i < DD; i += 32) acc += f[i] * Ws[i];
#pragma unroll
    for (int m = 16; m; m >>= 1) acc += __shfl_xor_sync(0xffffffffu, acc, m);
    if (lane == 0) sbuf[token] = 1.0f / (1.0f + expf(-(acc + bs[0])));
}

// ---------------------------------------------------------------------------
// Per-batch inclusive scan of sv, floor -> segment ids, max over valid
// ---------------------------------------------------------------------------
__global__ __launch_bounds__(1024)
void scan_kernel(const float* __restrict__ sbuf, const float* __restrict__ masks,
                 float* __restrict__ svbuf, int* __restrict__ segbuf,
                 float* __restrict__ maxseg)
{
    const int b = blockIdx.x;
    const int t = threadIdx.x;
    __shared__ float sc[SS];
    __shared__ float mr[SS];

    float valid = masks[b * SS + t];
    float sv = (valid > 0.0f) ? sbuf[b * SS + t] : 0.0f;
    svbuf[b * SS + t] = sv;
    sc[t] = sv;
    __syncthreads();
    for (int off = 1; off < SS; off <<= 1) {
        float vprev = (t >= off) ? sc[t - off] : 0.0f;
        __syncthreads();
        sc[t] += vprev;
        __syncthreads();
    }
    float c = floorf(sc[t]);
    int seg = (int)c;
    seg = seg < 0 ? 0 : (seg > SS - 1 ? SS - 1 : seg);
    segbuf[b * SS + t] = seg;

    mr[t] = (valid > 0.0f) ? c : -1.0f;
    __syncthreads();
    for (int off = 512; off > 0; off >>= 1) {
        if (t < off) mr[t] = fmaxf(mr[t], mr[t + off]);
        __syncthreads();
    }
    if (t == 0) maxseg[b] = mr[0];
}

// ---------------------------------------------------------------------------
// pooled[b,g,:] = sum_{s: seg[b,s]==g} x[b,s,:]*sv[b,s]
// ---------------------------------------------------------------------------
__global__ __launch_bounds__(256)
void pool_kernel(const float* __restrict__ x, const float* __restrict__ svbuf,
                 const int* __restrict__ segbuf, float* __restrict__ pooled)
{
    const int g = blockIdx.x;
    const int b = blockIdx.y;
    const int* seg = segbuf + b * SS;

    int lo = 0, hi = SS;
    while (lo < hi) { int mid = (lo + hi) >> 1; if (seg[mid] < g) lo = mid + 1; else hi = mid; }
    int beg = lo;
    lo = beg; hi = SS;
    while (lo < hi) { int mid = (lo + hi) >> 1; if (seg[mid] < g + 1) lo = mid + 1; else hi = mid; }
    int end = lo;

    const int t = threadIdx.x;
    float acc[4] = {0.0f, 0.0f, 0.0f, 0.0f};
    for (int s = beg; s < end; s++) {
        float w = svbuf[b * SS + s];
        const float* xr = x + ((size_t)b * SS + s) * DD;
#pragma unroll
        for (int i = 0; i < 4; i++) acc[i] += xr[t + i * 256] * w;
    }
    float* pr = pooled + ((size_t)b * SS + g) * DD;
#pragma unroll
    for (int i = 0; i < 4; i++) pr[t + i * 256] = acc[i];
}

// ---------------------------------------------------------------------------
// new_mask[b,s] = (s <= max_seg[b]) ? 1 : 0
// ---------------------------------------------------------------------------
__global__ __launch_bounds__(1024)
void mask_kernel(const float* __restrict__ maxseg, float* __restrict__ outmask)
{
    const int b = blockIdx.x;
    const int t = threadIdx.x;
    outmask[b * SS + t] = ((float)t <= maxseg[b]) ? 1.0f : 0.0f;
}

// ---------------------------------------------------------------------------
// Host side
// ---------------------------------------------------------------------------
static float* sym_addr_f(const void* sym) {
    void* p = nullptr;
    cudaGetSymbolAddress(&p, sym);
    return (float*)p;
}

static void launch_tgemm(const float* A, const float* Bt, const float* bias,
                         float* C, int M, int N, int K, int act) {
    dim3 grid(N / 128, M / 128);
    mma_gemm_kernel<<<grid, 256>>>(A, Bt, bias, C, M, N, K, act);
}

static void launch_transpose(const float* W, float* Wt, int Kd, int Nd) {
    transpose_kernel<<<dim3(Nd / 32, Kd / 32), 256>>>(W, Wt, Kd, Nd);
}

extern "C" void kernel_launch(void* const* d_in, const int* in_sizes, int n_in,
                              void* d_out, int out_size)
{
    (void)in_sizes; (void)n_in;
    const float* x     = (const float*)d_in[0];
    const float* masks = (const float*)d_in[1];
    const float* Wq  = (const float*)d_in[2];
    const float* bq  = (const float*)d_in[3];
    const float* Wk  = (const float*)d_in[4];
    const float* bk  = (const float*)d_in[5];
    const float* Wv  = (const float*)d_in[6];
    const float* bv  = (const float*)d_in[7];
    const float* Wo  = (const float*)d_in[8];
    const float* bo  = (const float*)d_in[9];
    const float* g1  = (const float*)d_in[10];
    const float* be1 = (const float*)d_in[11];
    const float* g2  = (const float*)d_in[12];
    const float* be2 = (const float*)d_in[13];
    const float* W1  = (const float*)d_in[14];
    const float* bf1 = (const float*)d_in[15];
    const float* W2  = (const float*)d_in[16];
    const float* bf2 = (const float*)d_in[17];
    const float* Ws  = (const float*)d_in[18];
    const float* bs  = (const float*)d_in[19];
    const float* P1  = (const float*)d_in[20];
    const float* bp1 = (const float*)d_in[21];
    const float* P2  = (const float*)d_in[22];
    const float* bp2 = (const float*)d_in[23];

    float* out = (float*)d_out;
    (void)out_size;

    float* qb    = sym_addr_f(g_q);
    float* kb2   = sym_addr_f(g_k);
    float* vb2   = sym_addr_f(g_v);
    float* attb  = sym_addr_f(g_att);
    float* ob    = sym_addr_f(g_o);
    float* hb    = sym_addr_f(g_h);
    float* featb = sym_addr_f(g_feat);
    float* feat2b= sym_addr_f(g_feat2);
    float* poolb = sym_addr_f(g_pool);
    float* ffb   = sym_addr_f(g_ff);
    float* phb   = sym_addr_f(g_ph);
    float* sb    = sym_addr_f(g_s);
    float* svb   = sym_addr_f(g_sv);
    int*   segb  = (int*)sym_addr_f(g_seg);
    float* msb   = sym_addr_f(g_maxseg);

    float* Wqt = sym_addr_f(g_wt_q);
    float* Wkt = sym_addr_f(g_wt_k);
    float* Wvt = sym_addr_f(g_wt_v);
    float* Wot = sym_addr_f(g_wt_o);
    float* W1t = sym_addr_f(g_wt_1);
    float* W2t = sym_addr_f(g_wt_2);
    float* P1t = sym_addr_f(g_wt_p1);
    float* P2t = sym_addr_f(g_wt_p2);

    // ---- transpose all weights to [N,K] (K contiguous) ----
    launch_transpose(Wq, Wqt, DD, DD);
    launch_transpose(Wk, Wkt, DD, DD);
    launch_transpose(Wv, Wvt, DD, DD);
    launch_transpose(Wo, Wot, DD, DD);
    launch_transpose(W1, W1t, DD, FF);
    launch_transpose(W2, W2t, FF, DD);
    launch_transpose(P1, P1t, DD, HID);
    launch_transpose(P2, P2t, HID, HID);

    // ---- encoder layer, applied twice ----
    const float* enc_in = x;
    float* enc_out = featb;
    for (int pass = 0; pass < 2; pass++) {
        int mode = pass;
        launch_tgemm(enc_in, Wqt, bq, qb,  TOK, DD, DD, 0);
        launch_tgemm(enc_in, Wkt, bk, kb2, TOK, DD, DD, 0);
        launch_tgemm(enc_in, Wvt, bv, vb2, TOK, DD, DD, 0);
        attn_kernel<<<dim3(SS / 64, BB * HH), 256>>>(qb, kb2, vb2, masks, mode, attb);
        launch_tgemm(attb, Wot, bo, ob, TOK, DD, DD, 0);
        add_ln_kernel<<<TOK, 256>>>(enc_in, ob, g1, be1, hb);
        launch_tgemm(hb, W1t, bf1, ffb, TOK, FF, DD, 1);   // GELU
        launch_tgemm(ffb, W2t, bf2, ob, TOK, DD, FF, 0);
        add_ln_kernel<<<TOK, 256>>>(hb, ob, g2, be2, enc_out);
        enc_in = featb;
        enc_out = feat2b;
    }

    // ---- importance scores, cumsum segmentation ----
    score_kernel<<<TOK / 8, 256>>>(feat2b, Ws, bs, sb);
    scan_kernel<<<BB, 1024>>>(sb, masks, svb, segb, msb);

    // ---- weighted segment-sum pooling of original x ----
    pool_kernel<<<dim3(SS, BB), 256>>>(x, svb, segb, poolb);

    // ---- projector ----
    launch_tgemm(poolb, P1t, bp1, phb, TOK, HID, DD, 1);   // GELU
    launch_tgemm(phb, P2t, bp2, out, TOK, HID, HID, 0);

    // ---- new_mask appended after the [B,S,HID] output ----
    mask_kernel<<<BB, 1024>>>(msb, out + (size_t)TOK * HID);
}

// round 4
// speedup vs baseline: 1.5159x; 1.1720x over previous
#include <cuda_runtime.h>
#include <cstdint>
#include <math.h>

// ---------------------------------------------------------------------------
// Problem constants
// ---------------------------------------------------------------------------
#define BB 4
#define SS 1024
#define DD 1024
#define HH 16
#define HDIM 64
#define FF 2048
#define HID 4096
#define TOK (BB*SS)          // 4096 tokens
#define QKVN 3072

// ---------------------------------------------------------------------------
// Scratch (__device__ globals; no allocation allowed)
// ---------------------------------------------------------------------------
__device__ float g_qkv [TOK*QKVN];
__device__ float g_att [TOK*DD];
__device__ float g_o   [TOK*DD];
__device__ float g_h   [TOK*DD];
__device__ float g_feat[TOK*DD];
__device__ float g_feat2[TOK*DD];
__device__ float g_pool[TOK*DD];
__device__ float g_ff  [TOK*FF];
__device__ float g_ph  [TOK*HID];
__device__ float g_s   [TOK];
__device__ float g_sv  [TOK];
__device__ int   g_seg [TOK];
__device__ float g_maxseg[BB];
__device__ float g_bqkv[QKVN];

// transposed weights [N,K] row-major (K contiguous) for the mma B operand
__device__ float g_wt_qkv[QKVN*DD];   // [Wq^T ; Wk^T ; Wv^T]
__device__ float g_wt_o [DD*DD];
__device__ float g_wt_1 [FF*DD];      // W1^T: [2048,1024]
__device__ float g_wt_2 [DD*FF];      // W2^T: [1024,2048]
__device__ float g_wt_p1[HID*DD];     // P1^T: [4096,1024]
__device__ float g_wt_p2[HID*HID];    // P2^T: [4096,4096]

// ---------------------------------------------------------------------------
// Helpers
// ---------------------------------------------------------------------------
__device__ __forceinline__ float gelu_f(float x) {
    return 0.5f * x * (1.0f + erff(x * 0.70710678118654752440f));
}

__device__ __forceinline__ void cp16(uint32_t dst, const void* src) {
    asm volatile("cp.async.cg.shared.global [%0], [%1], 16;\n"
                 :: "r"(dst), "l"(src));
}

__device__ __forceinline__ uint32_t smem_u32(const void* p) {
    uint32_t a;
    asm("{ .reg .u64 t; cvta.to.shared.u64 t, %1; cvt.u32.u64 %0, t; }"
        : "=r"(a) : "l"(p));
    return a;
}

// mma.sync m16n8k8 tf32: D += A*B
__device__ __forceinline__ void mma_tf32(float* c,
                                         uint32_t a0, uint32_t a1,
                                         uint32_t a2, uint32_t a3,
                                         uint32_t b0, uint32_t b1) {
    asm volatile(
        "mma.sync.aligned.m16n8k8.row.col.f32.tf32.tf32.f32 "
        "{%0,%1,%2,%3}, {%4,%5,%6,%7}, {%8,%9}, {%0,%1,%2,%3};\n"
        : "+f"(c[0]), "+f"(c[1]), "+f"(c[2]), "+f"(c[3])
        : "r"(a0), "r"(a1), "r"(a2), "r"(a3), "r"(b0), "r"(b1));
}

__device__ __forceinline__ void split1(float v, uint32_t& h, uint32_t& l) {
    uint32_t hb = __float_as_uint(v) & 0xFFFFE000u;
    h = hb;
    l = __float_as_uint(v - __uint_as_float(hb));
}

// ---------------------------------------------------------------------------
// tf32 tensor-core GEMM with exact 2-way split (fp32-equivalent accuracy)
// C[M,N] = act(A[M,K] @ Bt[N,K]^T + bias[N])
// ---------------------------------------------------------------------------
#define PAD 20

__global__ __launch_bounds__(256)
void mma_gemm_kernel(const float* __restrict__ A, const float* __restrict__ Bt,
                     const float* __restrict__ bias, float* __restrict__ C,
                     int M, int N, int K, int act)
{
    __shared__ float As[2][128 * PAD];
    __shared__ float Bs[2][128 * PAD];

    const int tid  = threadIdx.x;
    const int wid  = tid >> 5;
    const int lane = tid & 31;
    const int gr   = lane >> 2;     // 0..7
    const int gc   = lane & 3;      // 0..3
    const int row0 = blockIdx.y * 128;
    const int col0 = blockIdx.x * 128;
    const int warp_m = (wid & 3) * 32;
    const int warp_n = (wid >> 2) * 64;

    const uint32_t sA = smem_u32(&As[0][0]);
    const uint32_t sB = smem_u32(&Bs[0][0]);

    float acc[2][8][4];
#pragma unroll
    for (int i = 0; i < 2; i++)
#pragma unroll
        for (int j = 0; j < 8; j++)
#pragma unroll
            for (int r = 0; r < 4; r++) acc[i][j][r] = 0.0f;

    const int nk = K >> 4;
    const int m_a  = tid >> 2;
    const int kc_a = (tid & 3) << 2;

    {
#pragma unroll
        for (int j = 0; j < 2; j++) {
            int m = m_a + j * 64;
            cp16(sA + (uint32_t)(m * PAD + kc_a) * 4u,
                 A + (size_t)(row0 + m) * K + kc_a);
            cp16(sB + (uint32_t)(m * PAD + kc_a) * 4u,
                 Bt + (size_t)(col0 + m) * K + kc_a);
        }
        asm volatile("cp.async.commit_group;\n");
    }

    for (int t = 0; t < nk; t++) {
        const int st = t & 1;
        if (t + 1 < nk) {
            const int st2 = (t + 1) & 1;
            const int k0 = (t + 1) << 4;
#pragma unroll
            for (int j = 0; j < 2; j++) {
                int m = m_a + j * 64;
                cp16(sA + (uint32_t)(st2 * 128 * PAD + m * PAD + kc_a) * 4u,
                     A + (size_t)(row0 + m) * K + k0 + kc_a);
                cp16(sB + (uint32_t)(st2 * 128 * PAD + m * PAD + kc_a) * 4u,
                     Bt + (size_t)(col0 + m) * K + k0 + kc_a);
            }
            asm volatile("cp.async.commit_group;\n");
            asm volatile("cp.async.wait_group 1;\n");
        } else {
            asm volatile("cp.async.wait_group 0;\n");
        }
        __syncthreads();

        const float* as = &As[st][0];
        const float* bs = &Bs[st][0];

#pragma unroll
        for (int k8 = 0; k8 < 16; k8 += 8) {
            uint32_t ah[2][4], al[2][4];
#pragma unroll
            for (int mt = 0; mt < 2; mt++) {
                int base = (warp_m + mt * 16 + gr) * PAD + k8 + gc;
                split1(as[base],               ah[mt][0], al[mt][0]);
                split1(as[base + 8 * PAD],     ah[mt][1], al[mt][1]);
                split1(as[base + 4],           ah[mt][2], al[mt][2]);
                split1(as[base + 8 * PAD + 4], ah[mt][3], al[mt][3]);
            }
            uint32_t bh[8][2], bl[8][2];
#pragma unroll
            for (int nt = 0; nt < 8; nt++) {
                int base = (warp_n + nt * 8 + gr) * PAD + k8 + gc;
                split1(bs[base],     bh[nt][0], bl[nt][0]);
                split1(bs[base + 4], bh[nt][1], bl[nt][1]);
            }
#pragma unroll
            for (int mt = 0; mt < 2; mt++)
#pragma unroll
                for (int nt = 0; nt < 8; nt++) {
                    float* c = acc[mt][nt];
                    mma_tf32(c, ah[mt][0], ah[mt][1], ah[mt][2], ah[mt][3],
                             bh[nt][0], bh[nt][1]);
                    mma_tf32(c, ah[mt][0], ah[mt][1], ah[mt][2], ah[mt][3],
                             bl[nt][0], bl[nt][1]);
                    mma_tf32(c, al[mt][0], al[mt][1], al[mt][2], al[mt][3],
                             bh[nt][0], bh[nt][1]);
                }
        }
        __syncthreads();
    }

#pragma unroll
    for (int mt = 0; mt < 2; mt++) {
        const int r0 = row0 + warp_m + mt * 16 + gr;
#pragma unroll
        for (int nt = 0; nt < 8; nt++) {
            const int cc = col0 + warp_n + nt * 8 + 2 * gc;
            float b0v = bias[cc], b1v = bias[cc + 1];
            float v0 = acc[mt][nt][0] + b0v;
            float v1 = acc[mt][nt][1] + b1v;
            float v2 = acc[mt][nt][2] + b0v;
            float v3 = acc[mt][nt][3] + b1v;
            if (act == 1) {
                v0 = gelu_f(v0); v1 = gelu_f(v1);
                v2 = gelu_f(v2); v3 = gelu_f(v3);
            }
            *(float2*)(C + (size_t)r0 * N + cc)       = make_float2(v0, v1);
            *(float2*)(C + (size_t)(r0 + 8) * N + cc) = make_float2(v2, v3);
        }
    }
}

// ---------------------------------------------------------------------------
// Tensor-core flash attention (tf32 2-way split, 3 combos on both GEMMs).
// 128 threads = 4 warps; each warp: 16 queries x 64-key tile.
// qkv layout: [TOK, 3072] = [q(1024) | k(1024) | v(1024)], head slice h*64.
// Output o: [TOK, 1024].
// ---------------------------------------------------------------------------
#define AST 72   // smem row stride (floats): conflict-free fragment patterns
#define ATT_SMEM_BYTES (4 * 64 * AST * 4 + 64 * 4)

__global__ __launch_bounds__(128)
void attn_mma_kernel(const float* __restrict__ qkv, const float* __restrict__ masks,
                     int mode, float* __restrict__ o)
{
    extern __shared__ float smem[];
    float* Qs = smem;                 // [64][72]
    float* Ks = Qs + 64 * AST;
    float* Vs = Ks + 64 * AST;
    float* Ps = Vs + 64 * AST;
    float* mb = Ps + 64 * AST;        // [64]

    const int tid  = threadIdx.x;
    const int wid  = tid >> 5;
    const int lane = tid & 31;
    const int gr   = lane >> 2;
    const int gc   = lane & 3;
    const int q0   = blockIdx.x * 64;
    const int b    = blockIdx.y >> 4;
    const int h    = blockIdx.y & 15;
    const size_t qbase = (size_t)b * SS * QKVN + (size_t)h * HDIM;
    const size_t obase = (size_t)b * SS * DD + (size_t)h * HDIM;
    const int q0w = wid * 16;

    // load Q tile (pre-scaled by 1/sqrt(HD) = 0.125)
    for (int idx = tid; idx < 64 * 16; idx += 128) {
        int r = idx >> 4, c4 = (idx & 15) << 2;
        float4 v = *(const float4*)(qkv + qbase + (size_t)(q0 + r) * QKVN + c4);
        v.x *= 0.125f; v.y *= 0.125f; v.z *= 0.125f; v.w *= 0.125f;
        *(float4*)(Qs + r * AST + c4) = v;
    }

    float mrow[2] = {-1e30f, -1e30f};
    float lrow[2] = {0.0f, 0.0f};
    float Oacc[8][4];
#pragma unroll
    for (int i = 0; i < 8; i++)
#pragma unroll
        for (int j = 0; j < 4; j++) Oacc[i][j] = 0.0f;
    __syncthreads();

    for (int t = 0; t < 16; t++) {
        const int k0 = t * 64;
        for (int idx = tid; idx < 64 * 16; idx += 128) {
            int r = idx >> 4, c4 = (idx & 15) << 2;
            *(float4*)(Ks + r * AST + c4) =
                *(const float4*)(qkv + qbase + 1024 + (size_t)(k0 + r) * QKVN + c4);
            *(float4*)(Vs + r * AST + c4) =
                *(const float4*)(qkv + qbase + 2048 + (size_t)(k0 + r) * QKVN + c4);
        }
        if (tid < 64) {
            float mv = masks[b * SS + k0 + tid];
            mb[tid] = (mode == 0) ? mv : (mv > 0.0f ? 0.0f : -1e9f);
        }
        __syncthreads();

        // ---- scores: S(16q x 64k) = Q @ K^T
        float S[8][4];
#pragma unroll
        for (int i = 0; i < 8; i++)
#pragma unroll
            for (int j = 0; j < 4; j++) S[i][j] = 0.0f;

#pragma unroll
        for (int k8 = 0; k8 < 64; k8 += 8) {
            uint32_t ah[4], al[4];
            {
                int base = (q0w + gr) * AST + k8 + gc;
                split1(Qs[base],               ah[0], al[0]);
                split1(Qs[base + 8 * AST],     ah[1], al[1]);
                split1(Qs[base + 4],           ah[2], al[2]);
                split1(Qs[base + 8 * AST + 4], ah[3], al[3]);
            }
#pragma unroll
            for (int nt = 0; nt < 8; nt++) {
                int base = (nt * 8 + gr) * AST + k8 + gc;
                uint32_t bh0, bl0, bh1, bl1;
                split1(Ks[base],     bh0, bl0);
                split1(Ks[base + 4], bh1, bl1);
                mma_tf32(S[nt], ah[0], ah[1], ah[2], ah[3], bh0, bh1);
                mma_tf32(S[nt], ah[0], ah[1], ah[2], ah[3], bl0, bl1);
                mma_tf32(S[nt], al[0], al[1], al[2], al[3], bh0, bh1);
            }
        }

        // ---- bias + online softmax
        float rmax[2] = {-1e30f, -1e30f};
#pragma unroll
        for (int nt = 0; nt < 8; nt++) {
            float m0 = mb[nt * 8 + 2 * gc];
            float m1 = mb[nt * 8 + 2 * gc + 1];
            S[nt][0] += m0; S[nt][1] += m1;
            S[nt][2] += m0; S[nt][3] += m1;
            rmax[0] = fmaxf(rmax[0], fmaxf(S[nt][0], S[nt][1]));
            rmax[1] = fmaxf(rmax[1], fmaxf(S[nt][2], S[nt][3]));
        }
#pragma unroll
        for (int sh = 1; sh < 4; sh <<= 1) {
            rmax[0] = fmaxf(rmax[0], __shfl_xor_sync(0xffffffffu, rmax[0], sh));
            rmax[1] = fmaxf(rmax[1], __shfl_xor_sync(0xffffffffu, rmax[1], sh));
        }
        float mnew0 = fmaxf(mrow[0], rmax[0]);
        float mnew1 = fmaxf(mrow[1], rmax[1]);
        float scl0 = __expf(mrow[0] - mnew0);
        float scl1 = __expf(mrow[1] - mnew1);
        float rsum[2] = {0.0f, 0.0f};
#pragma unroll
        for (int nt = 0; nt < 8; nt++) {
            S[nt][0] = __expf(S[nt][0] - mnew0);
            S[nt][1] = __expf(S[nt][1] - mnew0);
            S[nt][2] = __expf(S[nt][2] - mnew1);
            S[nt][3] = __expf(S[nt][3] - mnew1);
            rsum[0] += S[nt][0] + S[nt][1];
            rsum[1] += S[nt][2] + S[nt][3];
        }
#pragma unroll
        for (int sh = 1; sh < 4; sh <<= 1) {
            rsum[0] += __shfl_xor_sync(0xffffffffu, rsum[0], sh);
            rsum[1] += __shfl_xor_sync(0xffffffffu, rsum[1], sh);
        }
        lrow[0] = lrow[0] * scl0 + rsum[0];
        lrow[1] = lrow[1] * scl1 + rsum[1];
        mrow[0] = mnew0; mrow[1] = mnew1;
#pragma unroll
        for (int dt = 0; dt < 8; dt++) {
            Oacc[dt][0] *= scl0; Oacc[dt][1] *= scl0;
            Oacc[dt][2] *= scl1; Oacc[dt][3] *= scl1;
        }

        // ---- stage P to smem (per-warp private rows; warp-local visibility)
        __syncwarp();
#pragma unroll
        for (int nt = 0; nt < 8; nt++) {
            int c0 = nt * 8 + 2 * gc;
            Ps[(q0w + gr) * AST + c0]         = S[nt][0];
            Ps[(q0w + gr) * AST + c0 + 1]     = S[nt][1];
            Ps[(q0w + gr + 8) * AST + c0]     = S[nt][2];
            Ps[(q0w + gr + 8) * AST + c0 + 1] = S[nt][3];
        }
        __syncwarp();

        // ---- O += P @ V
#pragma unroll
        for (int k8 = 0; k8 < 64; k8 += 8) {
            uint32_t ah[4], al[4];
            {
                int base = (q0w + gr) * AST + k8 + gc;
                split1(Ps[base],               ah[0], al[0]);
                split1(Ps[base + 8 * AST],     ah[1], al[1]);
                split1(Ps[base + 4],           ah[2], al[2]);
                split1(Ps[base + 8 * AST + 4], ah[3], al[3]);
            }
#pragma unroll
            for (int dt = 0; dt < 8; dt++) {
                uint32_t bh0, bl0, bh1, bl1;
                split1(Vs[(k8 + gc) * AST + dt * 8 + gr],     bh0, bl0);
                split1(Vs[(k8 + gc + 4) * AST + dt * 8 + gr], bh1, bl1);
                mma_tf32(Oacc[dt], ah[0], ah[1], ah[2], ah[3], bh0, bh1);
                mma_tf32(Oacc[dt], ah[0], ah[1], ah[2], ah[3], bl0, bl1);
                mma_tf32(Oacc[dt], al[0], al[1], al[2], al[3], bh0, bh1);
            }
        }
        __syncthreads();   // all warps done with K/V before next tile load
    }

    // ---- normalize + store
    float inv0 = 1.0f / lrow[0];
    float inv1 = 1.0f / lrow[1];
    const int r0 = q0 + q0w + gr;
#pragma unroll
    for (int dt = 0; dt < 8; dt++) {
        int col = dt * 8 + 2 * gc;
        *(float2*)(o + obase + (size_t)r0 * DD + col) =
            make_float2(Oacc[dt][0] * inv0, Oacc[dt][1] * inv0);
        *(float2*)(o + obase + (size_t)(r0 + 8) * DD + col) =
            make_float2(Oacc[dt][2] * inv1, Oacc[dt][3] * inv1);
    }
}

// ---------------------------------------------------------------------------
// Weight transpose: Wt[n,k] = W[k,n]
// ---------------------------------------------------------------------------
__global__ __launch_bounds__(256)
void transpose_kernel(const float* __restrict__ W, float* __restrict__ Wt,
                      int Kd, int Nd)
{
    __shared__ float t[32][33];
    const int n0 = blockIdx.x * 32, k0 = blockIdx.y * 32;
    const int tx = threadIdx.x & 31, ty = threadIdx.x >> 5;
#pragma unroll
    for (int r = ty; r < 32; r += 8)
        t[r][tx] = W[(size_t)(k0 + r) * Nd + n0 + tx];
    __syncthreads();
#pragma unroll
    for (int r = ty; r < 32; r += 8)
        Wt[(size_t)(n0 + r) * Kd + k0 + tx] = t[tx][r];
}

// ---------------------------------------------------------------------------
// concat bias [bq|bk|bv] -> bqkv
// ---------------------------------------------------------------------------
__global__ __launch_bounds__(256)
void concat_bias_kernel(const float* __restrict__ bq, const float* __restrict__ bk,
                        const float* __restrict__ bv, float* __restrict__ bqkv)
{
    int i = blockIdx.x * 256 + threadIdx.x;
    if (i < QKVN) {
        float v = (i < 1024) ? bq[i] : ((i < 2048) ? bk[i - 1024] : bv[i - 2048]);
        bqkv[i] = v;
    }
}

// ---------------------------------------------------------------------------
// out = LayerNorm(a + b) * g + beta
// ---------------------------------------------------------------------------
__global__ __launch_bounds__(256)
void add_ln_kernel(const float* __restrict__ a, const float* __restrict__ b2,
                   const float* __restrict__ g, const float* __restrict__ beta,
                   float* __restrict__ out)
{
    const int row = blockIdx.x;
    const size_t off = (size_t)row * DD;
    const int t = threadIdx.x;
    __shared__ float r1[256], r2[256];

    float vloc[4];
    float s = 0.0f, s2 = 0.0f;
#pragma unroll
    for (int i = 0; i < 4; i++) {
        int d = t + i * 256;
        float vv = a[off + d] + b2[off + d];
        vloc[i] = vv;
        s += vv; s2 += vv * vv;
    }
    r1[t] = s; r2[t] = s2;
    __syncthreads();
    for (int o2 = 128; o2 > 0; o2 >>= 1) {
        if (t < o2) { r1[t] += r1[t + o2]; r2[t] += r2[t + o2]; }
        __syncthreads();
    }
    float mean = r1[0] * (1.0f / DD);
    float var  = r2[0] * (1.0f / DD) - mean * mean;
    float inv  = rsqrtf(var + 1e-5f);
#pragma unroll
    for (int i = 0; i < 4; i++) {
        int d = t + i * 256;
        out[off + d] = (vloc[i] - mean) * inv * g[d] + beta[d];
    }
}

// ---------------------------------------------------------------------------
// s = sigmoid(feat @ Ws + bs); one warp per token
// ---------------------------------------------------------------------------
__global__ __launch_bounds__(256)
void score_kernel(const float* __restrict__ feat, const float* __restrict__ Ws,
                  const float* __restrict__ bs, float* __restrict__ sbuf)
{
    int token = blockIdx.x * 8 + (threadIdx.x >> 5);
    int lane  = threadIdx.x & 31;
    const float* f = feat + (size_t)token * DD;
    float acc = 0.0f;
    for (int i = lane; i < DD; i += 32) acc += f[i] * Ws[i];
#pragma unroll
    for (int m = 16; m; m >>= 1) acc += __shfl_xor_sync(0xffffffffu, acc, m);
    if (lane == 0) sbuf[token] = 1.0f / (1.0f + expf(-(acc + bs[0])));
}

// ---------------------------------------------------------------------------
// Per-batch inclusive scan of sv, floor -> segment ids, max over valid
// ---------------------------------------------------------------------------
__global__ __launch_bounds__(1024)
void scan_kernel(const float* __restrict__ sbuf, const float* __restrict__ masks,
                 float* __restrict__ svbuf, int* __restrict__ segbuf,
                 float* __restrict__ maxseg)
{
    const int b = blockIdx.x;
    const int t = threadIdx.x;
    __shared__ float sc[SS];
    __shared__ float mr[SS];

    float valid = masks[b * SS + t];
    float sv = (valid > 0.0f) ? sbuf[b * SS + t] : 0.0f;
    svbuf[b * SS + t] = sv;
    sc[t] = sv;
    __syncthreads();
    for (int off = 1; off < SS; off <<= 1) {
        float vprev = (t >= off) ? sc[t - off] : 0.0f;
        __syncthreads();
        sc[t] += vprev;
        __syncthreads();
    }
    float c = floorf(sc[t]);
    int seg = (int)c;
    seg = seg < 0 ? 0 : (seg > SS - 1 ? SS - 1 : seg);
    segbuf[b * SS + t] = seg;

    mr[t] = (valid > 0.0f) ? c : -1.0f;
    __syncthreads();
    for (int off = 512; off > 0; off >>= 1) {
        if (t < off) mr[t] = fmaxf(mr[t], mr[t + off]);
        __syncthreads();
    }
    if (t == 0) maxseg[b] = mr[0];
}

// ---------------------------------------------------------------------------
// pooled[b,g,:] = sum_{s: seg[b,s]==g} x[b,s,:]*sv[b,s]
// ---------------------------------------------------------------------------
__global__ __launch_bounds__(256)
void pool_kernel(const float* __restrict__ x, const float* __restrict__ svbuf,
                 const int* __restrict__ segbuf, float* __restrict__ pooled)
{
    const int g = blockIdx.x;
    const int b = blockIdx.y;
    const int* seg = segbuf + b * SS;

    int lo = 0, hi = SS;
    while (lo < hi) { int mid = (lo + hi) >> 1; if (seg[mid] < g) lo = mid + 1; else hi = mid; }
    int beg = lo;
    lo = beg; hi = SS;
    while (lo < hi) { int mid = (lo + hi) >> 1; if (seg[mid] < g + 1) lo = mid + 1; else hi = mid; }
    int end = lo;

    const int t = threadIdx.x;
    float acc[4] = {0.0f, 0.0f, 0.0f, 0.0f};
    for (int s = beg; s < end; s++) {
        float w = svbuf[b * SS + s];
        const float* xr = x + ((size_t)b * SS + s) * DD;
#pragma unroll
        for (int i = 0; i < 4; i++) acc[i] += xr[t + i * 256] * w;
    }
    float* pr = pooled + ((size_t)b * SS + g) * DD;
#pragma unroll
    for (int i = 0; i < 4; i++) pr[t + i * 256] = acc[i];
}

// ---------------------------------------------------------------------------
// new_mask[b,s] = (s <= max_seg[b]) ? 1 : 0
// ---------------------------------------------------------------------------
__global__ __launch_bounds__(1024)
void mask_kernel(const float* __restrict__ maxseg, float* __restrict__ outmask)
{
    const int b = blockIdx.x;
    const int t = threadIdx.x;
    outmask[b * SS + t] = ((float)t <= maxseg[b]) ? 1.0f : 0.0f;
}

// ---------------------------------------------------------------------------
// Host side
// ---------------------------------------------------------------------------
static float* sym_addr_f(const void* sym) {
    void* p = nullptr;
    cudaGetSymbolAddress(&p, sym);
    return (float*)p;
}

static void launch_tgemm(const float* A, const float* Bt, const float* bias,
                         float* C, int M, int N, int K, int act) {
    dim3 grid(N / 128, M / 128);
    mma_gemm_kernel<<<grid, 256>>>(A, Bt, bias, C, M, N, K, act);
}

static void launch_transpose(const float* W, float* Wt, int Kd, int Nd) {
    transpose_kernel<<<dim3(Nd / 32, Kd / 32), 256>>>(W, Wt, Kd, Nd);
}

extern "C" void kernel_launch(void* const* d_in, const int* in_sizes, int n_in,
                              void* d_out, int out_size)
{
    (void)in_sizes; (void)n_in;
    const float* x     = (const float*)d_in[0];
    const float* masks = (const float*)d_in[1];
    const float* Wq  = (const float*)d_in[2];
    const float* bq  = (const float*)d_in[3];
    const float* Wk  = (const float*)d_in[4];
    const float* bk  = (const float*)d_in[5];
    const float* Wv  = (const float*)d_in[6];
    const float* bv  = (const float*)d_in[7];
    const float* Wo  = (const float*)d_in[8];
    const float* bo  = (const float*)d_in[9];
    const float* g1  = (const float*)d_in[10];
    const float* be1 = (const float*)d_in[11];
    const float* g2  = (const float*)d_in[12];
    const float* be2 = (const float*)d_in[13];
    const float* W1  = (const float*)d_in[14];
    const float* bf1 = (const float*)d_in[15];
    const float* W2  = (const float*)d_in[16];
    const float* bf2 = (const float*)d_in[17];
    const float* Ws  = (const float*)d_in[18];
    const float* bs  = (const float*)d_in[19];
    const float* P1  = (const float*)d_in[20];
    const float* bp1 = (const float*)d_in[21];
    const float* P2  = (const float*)d_in[22];
    const float* bp2 = (const float*)d_in[23];

    float* out = (float*)d_out;
    (void)out_size;

    cudaFuncSetAttribute(attn_mma_kernel,
                         cudaFuncAttributeMaxDynamicSharedMemorySize,
                         ATT_SMEM_BYTES);

    float* qkvb  = sym_addr_f(g_qkv);
    float* attb  = sym_addr_f(g_att);
    float* ob    = sym_addr_f(g_o);
    float* hb    = sym_addr_f(g_h);
    float* featb = sym_addr_f(g_feat);
    float* feat2b= sym_addr_f(g_feat2);
    float* poolb = sym_addr_f(g_pool);
    float* ffb   = sym_addr_f(g_ff);
    float* phb   = sym_addr_f(g_ph);
    float* sb    = sym_addr_f(g_s);
    float* svb   = sym_addr_f(g_sv);
    int*   segb  = (int*)sym_addr_f(g_seg);
    float* msb   = sym_addr_f(g_maxseg);
    float* bqkvb = sym_addr_f(g_bqkv);

    float* Wqkvt = sym_addr_f(g_wt_qkv);
    float* Wot = sym_addr_f(g_wt_o);
    float* W1t = sym_addr_f(g_wt_1);
    float* W2t = sym_addr_f(g_wt_2);
    float* P1t = sym_addr_f(g_wt_p1);
    float* P2t = sym_addr_f(g_wt_p2);

    // ---- transpose all weights to [N,K] (K contiguous); QKV concatenated ----
    launch_transpose(Wq, Wqkvt,              DD, DD);
    launch_transpose(Wk, Wqkvt + DD * DD,    DD, DD);
    launch_transpose(Wv, Wqkvt + 2 * DD * DD, DD, DD);
    launch_transpose(Wo, Wot, DD, DD);
    launch_transpose(W1, W1t, DD, FF);
    launch_transpose(W2, W2t, FF, DD);
    launch_transpose(P1, P1t, DD, HID);
    launch_transpose(P2, P2t, HID, HID);
    concat_bias_kernel<<<(QKVN + 255) / 256, 256>>>(bq, bk, bv, bqkvb);

    // ---- encoder layer, applied twice ----
    const float* enc_in = x;
    float* enc_out = featb;
    for (int pass = 0; pass < 2; pass++) {
        int mode = pass;
        launch_tgemm(enc_in, Wqkvt, bqkvb, qkvb, TOK, QKVN, DD, 0);
        attn_mma_kernel<<<dim3(SS / 64, BB * HH), 128, ATT_SMEM_BYTES>>>(
            qkvb, masks, mode, attb);
        launch_tgemm(attb, Wot, bo, ob, TOK, DD, DD, 0);
        add_ln_kernel<<<TOK, 256>>>(enc_in, ob, g1, be1, hb);
        launch_tgemm(hb, W1t, bf1, ffb, TOK, FF, DD, 1);   // GELU
        launch_tgemm(ffb, W2t, bf2, ob, TOK, DD, FF, 0);
        add_ln_kernel<<<TOK, 256>>>(hb, ob, g2, be2, enc_out);
        enc_in = featb;
        enc_out = feat2b;
    }

    // ---- importance scores, cumsum segmentation ----
    score_kernel<<<TOK / 8, 256>>>(feat2b, Ws, bs, sb);
    scan_kernel<<<BB, 1024>>>(sb, masks, svb, segb, msb);

    // ---- weighted segment-sum pooling of original x ----
    pool_kernel<<<dim3(SS, BB), 256>>>(x, svb, segb, poolb);

    // ---- projector ----
    launch_tgemm(poolb, P1t, bp1, phb, TOK, HID, DD, 1);   // GELU
    launch_tgemm(phb, P2t, bp2, out, TOK, HID, HID, 0);

    // ---- new_mask appended after the [B,S,HID] output ----
    mask_kernel<<<BB, 1024>>>(msb, out + (size_t)TOK * HID);
}

// round 5
// speedup vs baseline: 1.7102x; 1.1282x over previous
#include <cuda_runtime.h>
#include <cuda_bf16.h>
#include <cstdint>
#include <math.h>

// ---------------------------------------------------------------------------
// Problem constants
// ---------------------------------------------------------------------------
#define BB 4
#define SS 1024
#define DD 1024
#define HH 16
#define HDIM 64
#define FF 2048
#define HID 4096
#define TOK (BB*SS)          // 4096 tokens
#define QKVN 3072

// ---------------------------------------------------------------------------
// Scratch (__device__ globals; no allocation allowed)
// ---------------------------------------------------------------------------
__device__ float g_qkv [TOK*QKVN];
__device__ float g_att [TOK*DD];
__device__ float g_o   [TOK*DD];
__device__ float g_h   [TOK*DD];
__device__ float g_feat[TOK*DD];
__device__ float g_feat2[TOK*DD];
__device__ float g_ff  [TOK*FF];
__device__ float g_s   [TOK];
__device__ float g_sv  [TOK];
__device__ int   g_seg [TOK];
__device__ float g_maxseg[BB];
__device__ float g_bqkv[QKVN];

// tf32-path transposed weights [N,K] (K contiguous)
__device__ float g_wt_qkv[QKVN*DD];   // [Wq^T ; Wk^T ; Wv^T]
__device__ float g_wt_o [DD*DD];
__device__ float g_wt_1 [FF*DD];
__device__ float g_wt_2 [DD*FF];

// bf16-split projector operands
__device__ __nv_bfloat16 g_p1h[HID*DD],  g_p1l[HID*DD];    // P1^T split
__device__ __nv_bfloat16 g_p2h[HID*HID], g_p2l[HID*HID];   // P2^T split
__device__ __nv_bfloat16 g_poolh[TOK*DD],  g_pooll[TOK*DD];
__device__ __nv_bfloat16 g_phh[TOK*HID],   g_phl[TOK*HID];

// ---------------------------------------------------------------------------
// Helpers
// ---------------------------------------------------------------------------
__device__ __forceinline__ float gelu_f(float x) {
    return 0.5f * x * (1.0f + erff(x * 0.70710678118654752440f));
}

__device__ __forceinline__ void cp16(uint32_t dst, const void* src) {
    asm volatile("cp.async.cg.shared.global [%0], [%1], 16;\n"
                 :: "r"(dst), "l"(src));
}

__device__ __forceinline__ uint32_t smem_u32(const void* p) {
    uint32_t a;
    asm("{ .reg .u64 t; cvta.to.shared.u64 t, %1; cvt.u32.u64 %0, t; }"
        : "=r"(a) : "l"(p));
    return a;
}

// mma.sync m16n8k8 tf32: D += A*B
__device__ __forceinline__ void mma_tf32(float* c,
                                         uint32_t a0, uint32_t a1,
                                         uint32_t a2, uint32_t a3,
                                         uint32_t b0, uint32_t b1) {
    asm volatile(
        "mma.sync.aligned.m16n8k8.row.col.f32.tf32.tf32.f32 "
        "{%0,%1,%2,%3}, {%4,%5,%6,%7}, {%8,%9}, {%0,%1,%2,%3};\n"
        : "+f"(c[0]), "+f"(c[1]), "+f"(c[2]), "+f"(c[3])
        : "r"(a0), "r"(a1), "r"(a2), "r"(a3), "r"(b0), "r"(b1));
}

// mma.sync m16n8k16 bf16: D += A*B
__device__ __forceinline__ void mma_bf16(float* c,
                                         uint32_t a0, uint32_t a1,
                                         uint32_t a2, uint32_t a3,
                                         uint32_t b0, uint32_t b1) {
    asm volatile(
        "mma.sync.aligned.m16n8k16.row.col.f32.bf16.bf16.f32 "
        "{%0,%1,%2,%3}, {%4,%5,%6,%7}, {%8,%9}, {%0,%1,%2,%3};\n"
        : "+f"(c[0]), "+f"(c[1]), "+f"(c[2]), "+f"(c[3])
        : "r"(a0), "r"(a1), "r"(a2), "r"(a3), "r"(b0), "r"(b1));
}

__device__ __forceinline__ void split1(float v, uint32_t& h, uint32_t& l) {
    uint32_t hb = __float_as_uint(v) & 0xFFFFE000u;
    h = hb;
    l = __float_as_uint(v - __uint_as_float(hb));
}

__device__ __forceinline__ void bsplit(float v, __nv_bfloat16& h, __nv_bfloat16& l) {
    h = __float2bfloat16(v);
    l = __float2bfloat16(v - __bfloat162float(h));
}

// ---------------------------------------------------------------------------
// tf32 tensor-core GEMM with exact 2-way split (fp32-equivalent accuracy)
// C[M,N] = act(A[M,K] @ Bt[N,K]^T + bias[N])
// ---------------------------------------------------------------------------
#define PAD 20

__global__ __launch_bounds__(256)
void mma_gemm_kernel(const float* __restrict__ A, const float* __restrict__ Bt,
                     const float* __restrict__ bias, float* __restrict__ C,
                     int M, int N, int K, int act)
{
    __shared__ float As[2][128 * PAD];
    __shared__ float Bs[2][128 * PAD];

    const int tid  = threadIdx.x;
    const int wid  = tid >> 5;
    const int lane = tid & 31;
    const int gr   = lane >> 2;
    const int gc   = lane & 3;
    const int row0 = blockIdx.y * 128;
    const int col0 = blockIdx.x * 128;
    const int warp_m = (wid & 3) * 32;
    const int warp_n = (wid >> 2) * 64;

    const uint32_t sA = smem_u32(&As[0][0]);
    const uint32_t sB = smem_u32(&Bs[0][0]);

    float acc[2][8][4];
#pragma unroll
    for (int i = 0; i < 2; i++)
#pragma unroll
        for (int j = 0; j < 8; j++)
#pragma unroll
            for (int r = 0; r < 4; r++) acc[i][j][r] = 0.0f;

    const int nk = K >> 4;
    const int m_a  = tid >> 2;
    const int kc_a = (tid & 3) << 2;

    {
#pragma unroll
        for (int j = 0; j < 2; j++) {
            int m = m_a + j * 64;
            cp16(sA + (uint32_t)(m * PAD + kc_a) * 4u,
                 A + (size_t)(row0 + m) * K + kc_a);
            cp16(sB + (uint32_t)(m * PAD + kc_a) * 4u,
                 Bt + (size_t)(col0 + m) * K + kc_a);
        }
        asm volatile("cp.async.commit_group;\n");
    }

    for (int t = 0; t < nk; t++) {
        const int st = t & 1;
        if (t + 1 < nk) {
            const int st2 = (t + 1) & 1;
            const int k0 = (t + 1) << 4;
#pragma unroll
            for (int j = 0; j < 2; j++) {
                int m = m_a + j * 64;
                cp16(sA + (uint32_t)(st2 * 128 * PAD + m * PAD + kc_a) * 4u,
                     A + (size_t)(row0 + m) * K + k0 + kc_a);
                cp16(sB + (uint32_t)(st2 * 128 * PAD + m * PAD + kc_a) * 4u,
                     Bt + (size_t)(col0 + m) * K + k0 + kc_a);
            }
            asm volatile("cp.async.commit_group;\n");
            asm volatile("cp.async.wait_group 1;\n");
        } else {
            asm volatile("cp.async.wait_group 0;\n");
        }
        __syncthreads();

        const float* as = &As[st][0];
        const float* bs = &Bs[st][0];

#pragma unroll
        for (int k8 = 0; k8 < 16; k8 += 8) {
            uint32_t ah[2][4], al[2][4];
#pragma unroll
            for (int mt = 0; mt < 2; mt++) {
                int base = (warp_m + mt * 16 + gr) * PAD + k8 + gc;
                split1(as[base],               ah[mt][0], al[mt][0]);
                split1(as[base + 8 * PAD],     ah[mt][1], al[mt][1]);
                split1(as[base + 4],           ah[mt][2], al[mt][2]);
                split1(as[base + 8 * PAD + 4], ah[mt][3], al[mt][3]);
            }
            uint32_t bh[8][2], bl[8][2];
#pragma unroll
            for (int nt = 0; nt < 8; nt++) {
                int base = (warp_n + nt * 8 + gr) * PAD + k8 + gc;
                split1(bs[base],     bh[nt][0], bl[nt][0]);
                split1(bs[base + 4], bh[nt][1], bl[nt][1]);
            }
#pragma unroll
            for (int mt = 0; mt < 2; mt++)
#pragma unroll
                for (int nt = 0; nt < 8; nt++) {
                    float* c = acc[mt][nt];
                    mma_tf32(c, ah[mt][0], ah[mt][1], ah[mt][2], ah[mt][3],
                             bh[nt][0], bh[nt][1]);
                    mma_tf32(c, ah[mt][0], ah[mt][1], ah[mt][2], ah[mt][3],
                             bl[nt][0], bl[nt][1]);
                    mma_tf32(c, al[mt][0], al[mt][1], al[mt][2], al[mt][3],
                             bh[nt][0], bh[nt][1]);
                }
        }
        __syncthreads();
    }

#pragma unroll
    for (int mt = 0; mt < 2; mt++) {
        const int r0 = row0 + warp_m + mt * 16 + gr;
#pragma unroll
        for (int nt = 0; nt < 8; nt++) {
            const int cc = col0 + warp_n + nt * 8 + 2 * gc;
            float b0v = bias[cc], b1v = bias[cc + 1];
            float v0 = acc[mt][nt][0] + b0v;
            float v1 = acc[mt][nt][1] + b1v;
            float v2 = acc[mt][nt][2] + b0v;
            float v3 = acc[mt][nt][3] + b1v;
            if (act == 1) {
                v0 = gelu_f(v0); v1 = gelu_f(v1);
                v2 = gelu_f(v2); v3 = gelu_f(v3);
            }
            *(float2*)(C + (size_t)r0 * N + cc)       = make_float2(v0, v1);
            *(float2*)(C + (size_t)(r0 + 8) * N + cc) = make_float2(v2, v3);
        }
    }
}

// ---------------------------------------------------------------------------
// bf16 split GEMM: C = act(A @ Bt^T + bias), A = Ah+Al, Bt = Bh+Bl (bf16 pairs)
// 3 combos (hh, hl, lh) on mma.sync m16n8k16 -> ~16-bit mantissa accuracy.
// BM=BN=128, BK=32 halves/stage. smem row stride 40 halves (conflict-free).
// out_split: write split bf16 (Ch, Cl) instead of fp32 C.
// ---------------------------------------------------------------------------
#define HS 40
#define BF_STAGE_HALVES 20480          // 4 arrays * 128*40
#define BF_SMEM_BYTES  (2 * BF_STAGE_HALVES * 2)

__global__ __launch_bounds__(256)
void bf16_gemm_kernel(const __nv_bfloat16* __restrict__ Ah,
                      const __nv_bfloat16* __restrict__ Al,
                      const __nv_bfloat16* __restrict__ Bh,
                      const __nv_bfloat16* __restrict__ Bl,
                      const float* __restrict__ bias, float* __restrict__ C,
                      __nv_bfloat16* __restrict__ Ch, __nv_bfloat16* __restrict__ Cl,
                      int M, int N, int K, int act, int out_split)
{
    extern __shared__ __nv_bfloat16 hsm[];
    const int tid  = threadIdx.x;
    const int wid  = tid >> 5;
    const int lane = tid & 31;
    const int gr   = lane >> 2;
    const int gc   = lane & 3;
    const int row0 = blockIdx.y * 128;
    const int col0 = blockIdx.x * 128;
    const int warp_m = (wid & 3) * 32;
    const int warp_n = (wid >> 2) * 64;
    const uint32_t sbase = smem_u32(hsm);

    float acc[2][8][4];
#pragma unroll
    for (int i = 0; i < 2; i++)
#pragma unroll
        for (int j = 0; j < 8; j++)
#pragma unroll
            for (int r = 0; r < 4; r++) acc[i][j][r] = 0.0f;

    const int nk = K >> 5;   // 32 halves per stage
    // per-thread load assignment: 2 chunks (16B = 8 halves) per array
    const int c0i = tid * 2, c1i = tid * 2 + 1;
    const int m0 = c0i >> 2, kc0 = (c0i & 3) * 8;
    const int m1 = c1i >> 2, kc1 = (c1i & 3) * 8;

#define BF_LOAD_STAGE(st, k0)                                                    \
    do {                                                                         \
        uint32_t b = sbase + (uint32_t)(st) * BF_STAGE_HALVES * 2u;              \
        cp16(b + (uint32_t)(m0 * HS + kc0) * 2u,                                 \
             Ah + (size_t)(row0 + m0) * K + (k0) + kc0);                         \
        cp16(b + (uint32_t)(m1 * HS + kc1) * 2u,                                 \
             Ah + (size_t)(row0 + m1) * K + (k0) + kc1);                         \
        cp16(b + (uint32_t)(5120 + m0 * HS + kc0) * 2u,                          \
             Al + (size_t)(row0 + m0) * K + (k0) + kc0);                         \
        cp16(b + (uint32_t)(5120 + m1 * HS + kc1) * 2u,                          \
             Al + (size_t)(row0 + m1) * K + (k0) + kc1);                         \
        cp16(b + (uint32_t)(10240 + m0 * HS + kc0) * 2u,                         \
             Bh + (size_t)(col0 + m0) * K + (k0) + kc0);                         \
        cp16(b + (uint32_t)(10240 + m1 * HS + kc1) * 2u,                         \
             Bh + (size_t)(col0 + m1) * K + (k0) + kc1);                         \
        cp16(b + (uint32_t)(15360 + m0 * HS + kc0) * 2u,                         \
             Bl + (size_t)(col0 + m0) * K + (k0) + kc0);                         \
        cp16(b + (uint32_t)(15360 + m1 * HS + kc1) * 2u,                         \
             Bl + (size_t)(col0 + m1) * K + (k0) + kc1);                         \
        asm volatile("cp.async.commit_group;\n");                                \
    } while (0)

    BF_LOAD_STAGE(0, 0);

    for (int t = 0; t < nk; t++) {
        const int st = t & 1;
        if (t + 1 < nk) {
            BF_LOAD_STAGE((t + 1) & 1, (t + 1) << 5);
            asm volatile("cp.async.wait_group 1;\n");
        } else {
            asm volatile("cp.async.wait_group 0;\n");
        }
        __syncthreads();

        const __nv_bfloat16* s = hsm + st * BF_STAGE_HALVES;

#pragma unroll
        for (int ks = 0; ks < 2; ks++) {
            const int kh = ks * 16;
            uint32_t ahf[2][4], alf[2][4];
#pragma unroll
            for (int mt = 0; mt < 2; mt++) {
                int r = warp_m + mt * 16 + gr;
                ahf[mt][0] = *(const uint32_t*)(s + r * HS + kh + 2 * gc);
                ahf[mt][1] = *(const uint32_t*)(s + (r + 8) * HS + kh + 2 * gc);
                ahf[mt][2] = *(const uint32_t*)(s + r * HS + kh + 8 + 2 * gc);
                ahf[mt][3] = *(const uint32_t*)(s + (r + 8) * HS + kh + 8 + 2 * gc);
                alf[mt][0] = *(const uint32_t*)(s + 5120 + r * HS + kh + 2 * gc);
                alf[mt][1] = *(const uint32_t*)(s + 5120 + (r + 8) * HS + kh + 2 * gc);
                alf[mt][2] = *(const uint32_t*)(s + 5120 + r * HS + kh + 8 + 2 * gc);
                alf[mt][3] = *(const uint32_t*)(s + 5120 + (r + 8) * HS + kh + 8 + 2 * gc);
            }
#pragma unroll
            for (int nt = 0; nt < 8; nt++) {
                int r = warp_n + nt * 8 + gr;
                uint32_t bh0 = *(const uint32_t*)(s + 10240 + r * HS + kh + 2 * gc);
                uint32_t bh1 = *(const uint32_t*)(s + 10240 + r * HS + kh + 8 + 2 * gc);
                uint32_t bl0 = *(const uint32_t*)(s + 15360 + r * HS + kh + 2 * gc);
                uint32_t bl1 = *(const uint32_t*)(s + 15360 + r * HS + kh + 8 + 2 * gc);
#pragma unroll
                for (int mt = 0; mt < 2; mt++) {
                    float* c = acc[mt][nt];
                    mma_bf16(c, ahf[mt][0], ahf[mt][1], ahf[mt][2], ahf[mt][3], bh0, bh1);
                    mma_bf16(c, ahf[mt][0], ahf[mt][1], ahf[mt][2], ahf[mt][3], bl0, bl1);
                    mma_bf16(c, alf[mt][0], alf[mt][1], alf[mt][2], alf[mt][3], bh0, bh1);
                }
            }
        }
        __syncthreads();
    }

#pragma unroll
    for (int mt = 0; mt < 2; mt++) {
        const int r0 = row0 + warp_m + mt * 16 + gr;
#pragma unroll
        for (int nt = 0; nt < 8; nt++) {
            const int cc = col0 + warp_n + nt * 8 + 2 * gc;
            float b0v = bias[cc], b1v = bias[cc + 1];
            float v0 = acc[mt][nt][0] + b0v;
            float v1 = acc[mt][nt][1] + b1v;
            float v2 = acc[mt][nt][2] + b0v;
            float v3 = acc[mt][nt][3] + b1v;
            if (act == 1) {
                v0 = gelu_f(v0); v1 = gelu_f(v1);
                v2 = gelu_f(v2); v3 = gelu_f(v3);
            }
            if (!out_split) {
                *(float2*)(C + (size_t)r0 * N + cc)       = make_float2(v0, v1);
                *(float2*)(C + (size_t)(r0 + 8) * N + cc) = make_float2(v2, v3);
            } else {
                __nv_bfloat16 h0, l0, h1, l1;
                bsplit(v0, h0, l0); bsplit(v1, h1, l1);
                *(__nv_bfloat162*)(Ch + (size_t)r0 * N + cc) =
                    __nv_bfloat162(h0, h1);
                *(__nv_bfloat162*)(Cl + (size_t)r0 * N + cc) =
                    __nv_bfloat162(l0, l1);
                bsplit(v2, h0, l0); bsplit(v3, h1, l1);
                *(__nv_bfloat162*)(Ch + (size_t)(r0 + 8) * N + cc) =
                    __nv_bfloat162(h0, h1);
                *(__nv_bfloat162*)(Cl + (size_t)(r0 + 8) * N + cc) =
                    __nv_bfloat162(l0, l1);
            }
        }
    }
}

// ---------------------------------------------------------------------------
// Tensor-core flash attention (tf32 2-way split, 3 combos on both GEMMs).
// ---------------------------------------------------------------------------
#define AST 72
#define ATT_SMEM_BYTES (4 * 64 * AST * 4 + 64 * 4)

__global__ __launch_bounds__(128)
void attn_mma_kernel(const float* __restrict__ qkv, const float* __restrict__ masks,
                     int mode, float* __restrict__ o)
{
    extern __shared__ float smem[];
    float* Qs = smem;
    float* Ks = Qs + 64 * AST;
    float* Vs = Ks + 64 * AST;
    float* Ps = Vs + 64 * AST;
    float* mb = Ps + 64 * AST;

    const int tid  = threadIdx.x;
    const int wid  = tid >> 5;
    const int lane = tid & 31;
    const int gr   = lane >> 2;
    const int gc   = lane & 3;
    const int q0   = blockIdx.x * 64;
    const int b    = blockIdx.y >> 4;
    const int h    = blockIdx.y & 15;
    const size_t qbase = (size_t)b * SS * QKVN + (size_t)h * HDIM;
    const size_t obase = (size_t)b * SS * DD + (size_t)h * HDIM;
    const int q0w = wid * 16;

    for (int idx = tid; idx < 64 * 16; idx += 128) {
        int r = idx >> 4, c4 = (idx & 15) << 2;
        float4 v = *(const float4*)(qkv + qbase + (size_t)(q0 + r) * QKVN + c4);
        v.x *= 0.125f; v.y *= 0.125f; v.z *= 0.125f; v.w *= 0.125f;
        *(float4*)(Qs + r * AST + c4) = v;
    }

    float mrow[2] = {-1e30f, -1e30f};
    float lrow[2] = {0.0f, 0.0f};
    float Oacc[8][4];
#pragma unroll
    for (int i = 0; i < 8; i++)
#pragma unroll
        for (int j = 0; j < 4; j++) Oacc[i][j] = 0.0f;
    __syncthreads();

    for (int t = 0; t < 16; t++) {
        const int k0 = t * 64;
        for (int idx = tid; idx < 64 * 16; idx += 128) {
            int r = idx >> 4, c4 = (idx & 15) << 2;
            *(float4*)(Ks + r * AST + c4) =
                *(const float4*)(qkv + qbase + 1024 + (size_t)(k0 + r) * QKVN + c4);
            *(float4*)(Vs + r * AST + c4) =
                *(const float4*)(qkv + qbase + 2048 + (size_t)(k0 + r) * QKVN + c4);
        }
        if (tid < 64) {
            float mv = masks[b * SS + k0 + tid];
            mb[tid] = (mode == 0) ? mv : (mv > 0.0f ? 0.0f : -1e9f);
        }
        __syncthreads();

        float S[8][4];
#pragma unroll
        for (int i = 0; i < 8; i++)
#pragma unroll
            for (int j = 0; j < 4; j++) S[i][j] = 0.0f;

#pragma unroll
        for (int k8 = 0; k8 < 64; k8 += 8) {
            uint32_t ah[4], al[4];
            {
                int base = (q0w + gr) * AST + k8 + gc;
                split1(Qs[base],               ah[0], al[0]);
                split1(Qs[base + 8 * AST],     ah[1], al[1]);
                split1(Qs[base + 4],           ah[2], al[2]);
                split1(Qs[base + 8 * AST + 4], ah[3], al[3]);
            }
#pragma unroll
            for (int nt = 0; nt < 8; nt++) {
                int base = (nt * 8 + gr) * AST + k8 + gc;
                uint32_t bh0, bl0, bh1, bl1;
                split1(Ks[base],     bh0, bl0);
                split1(Ks[base + 4], bh1, bl1);
                mma_tf32(S[nt], ah[0], ah[1], ah[2], ah[3], bh0, bh1);
                mma_tf32(S[nt], ah[0], ah[1], ah[2], ah[3], bl0, bl1);
                mma_tf32(S[nt], al[0], al[1], al[2], al[3], bh0, bh1);
            }
        }

        float rmax[2] = {-1e30f, -1e30f};
#pragma unroll
        for (int nt = 0; nt < 8; nt++) {
            float m0 = mb[nt * 8 + 2 * gc];
            float m1 = mb[nt * 8 + 2 * gc + 1];
            S[nt][0] += m0; S[nt][1] += m1;
            S[nt][2] += m0; S[nt][3] += m1;
            rmax[0] = fmaxf(rmax[0], fmaxf(S[nt][0], S[nt][1]));
            rmax[1] = fmaxf(rmax[1], fmaxf(S[nt][2], S[nt][3]));
        }
#pragma unroll
        for (int sh = 1; sh < 4; sh <<= 1) {
            rmax[0] = fmaxf(rmax[0], __shfl_xor_sync(0xffffffffu, rmax[0], sh));
            rmax[1] = fmaxf(rmax[1], __shfl_xor_sync(0xffffffffu, rmax[1], sh));
        }
        float mnew0 = fmaxf(mrow[0], rmax[0]);
        float mnew1 = fmaxf(mrow[1], rmax[1]);
        float scl0 = __expf(mrow[0] - mnew0);
        float scl1 = __expf(mrow[1] - mnew1);
        float rsum[2] = {0.0f, 0.0f};
#pragma unroll
        for (int nt = 0; nt < 8; nt++) {
            S[nt][0] = __expf(S[nt][0] - mnew0);
            S[nt][1] = __expf(S[nt][1] - mnew0);
            S[nt][2] = __expf(S[nt][2] - mnew1);
            S[nt][3] = __expf(S[nt][3] - mnew1);
            rsum[0] += S[nt][0] + S[nt][1];
            rsum[1] += S[nt][2] + S[nt][3];
        }
#pragma unroll
        for (int sh = 1; sh < 4; sh <<= 1) {
            rsum[0] += __shfl_xor_sync(0xffffffffu, rsum[0], sh);
            rsum[1] += __shfl_xor_sync(0xffffffffu, rsum[1], sh);
        }
        lrow[0] = lrow[0] * scl0 + rsum[0];
        lrow[1] = lrow[1] * scl1 + rsum[1];
        mrow[0] = mnew0; mrow[1] = mnew1;
#pragma unroll
        for (int dt = 0; dt < 8; dt++) {
            Oacc[dt][0] *= scl0; Oacc[dt][1] *= scl0;
            Oacc[dt][2] *= scl1; Oacc[dt][3] *= scl1;
        }

        __syncwarp();
#pragma unroll
        for (int nt = 0; nt < 8; nt++) {
            int c0 = nt * 8 + 2 * gc;
            Ps[(q0w + gr) * AST + c0]         = S[nt][0];
            Ps[(q0w + gr) * AST + c0 + 1]     = S[nt][1];
            Ps[(q0w + gr + 8) * AST + c0]     = S[nt][2];
            Ps[(q0w + gr + 8) * AST + c0 + 1] = S[nt][3];
        }
        __syncwarp();

#pragma unroll
        for (int k8 = 0; k8 < 64; k8 += 8) {
            uint32_t ah[4], al[4];
            {
                int base = (q0w + gr) * AST + k8 + gc;
                split1(Ps[base],               ah[0], al[0]);
                split1(Ps[base + 8 * AST],     ah[1], al[1]);
                split1(Ps[base + 4],           ah[2], al[2]);
                split1(Ps[base + 8 * AST + 4], ah[3], al[3]);
            }
#pragma unroll
            for (int dt = 0; dt < 8; dt++) {
                uint32_t bh0, bl0, bh1, bl1;
                split1(Vs[(k8 + gc) * AST + dt * 8 + gr],     bh0, bl0);
                split1(Vs[(k8 + gc + 4) * AST + dt * 8 + gr], bh1, bl1);
                mma_tf32(Oacc[dt], ah[0], ah[1], ah[2], ah[3], bh0, bh1);
                mma_tf32(Oacc[dt], ah[0], ah[1], ah[2], ah[3], bl0, bl1);
                mma_tf32(Oacc[dt], al[0], al[1], al[2], al[3], bh0, bh1);
            }
        }
        __syncthreads();
    }

    float inv0 = 1.0f / lrow[0];
    float inv1 = 1.0f / lrow[1];
    const int r0 = q0 + q0w + gr;
#pragma unroll
    for (int dt = 0; dt < 8; dt++) {
        int col = dt * 8 + 2 * gc;
        *(float2*)(o + obase + (size_t)r0 * DD + col) =
            make_float2(Oacc[dt][0] * inv0, Oacc[dt][1] * inv0);
        *(float2*)(o + obase + (size_t)(r0 + 8) * DD + col) =
            make_float2(Oacc[dt][2] * inv1, Oacc[dt][3] * inv1);
    }
}

// ---------------------------------------------------------------------------
// Weight transpose: Wt[n,k] = W[k,n] (fp32)
// ---------------------------------------------------------------------------
__global__ __launch_bounds__(256)
void transpose_kernel(const float* __restrict__ W, float* __restrict__ Wt,
                      int Kd, int Nd)
{
    __shared__ float t[32][33];
    const int n0 = blockIdx.x * 32, k0 = blockIdx.y * 32;
    const int tx = threadIdx.x & 31, ty = threadIdx.x >> 5;
#pragma unroll
    for (int r = ty; r < 32; r += 8)
        t[r][tx] = W[(size_t)(k0 + r) * Nd + n0 + tx];
    __syncthreads();
#pragma unroll
    for (int r = ty; r < 32; r += 8)
        Wt[(size_t)(n0 + r) * Kd + k0 + tx] = t[tx][r];
}

// ---------------------------------------------------------------------------
// Transpose + bf16 split: Wh/Wl[n,k] = split(W[k,n])
// ---------------------------------------------------------------------------
__global__ __launch_bounds__(256)
void trans_split_kernel(const float* __restrict__ W,
                        __nv_bfloat16* __restrict__ Wh,
                        __nv_bfloat16* __restrict__ Wl, int Kd, int Nd)
{
    __shared__ float t[32][33];
    const int n0 = blockIdx.x * 32, k0 = blockIdx.y * 32;
    const int tx = threadIdx.x & 31, ty = threadIdx.x >> 5;
#pragma unroll
    for (int r = ty; r < 32; r += 8)
        t[r][tx] = W[(size_t)(k0 + r) * Nd + n0 + tx];
    __syncthreads();
#pragma unroll
    for (int r = ty; r < 32; r += 8) {
        float v = t[tx][r];
        __nv_bfloat16 h, l;
        bsplit(v, h, l);
        Wh[(size_t)(n0 + r) * Kd + k0 + tx] = h;
        Wl[(size_t)(n0 + r) * Kd + k0 + tx] = l;
    }
}

// ---------------------------------------------------------------------------
// concat bias [bq|bk|bv] -> bqkv
// ---------------------------------------------------------------------------
__global__ __launch_bounds__(256)
void concat_bias_kernel(const float* __restrict__ bq, const float* __restrict__ bk,
                        const float* __restrict__ bv, float* __restrict__ bqkv)
{
    int i = blockIdx.x * 256 + threadIdx.x;
    if (i < QKVN) {
        float v = (i < 1024) ? bq[i] : ((i < 2048) ? bk[i - 1024] : bv[i - 2048]);
        bqkv[i] = v;
    }
}

// ---------------------------------------------------------------------------
// out = LayerNorm(a + b) * g + beta
// ---------------------------------------------------------------------------
__global__ __launch_bounds__(256)
void add_ln_kernel(const float* __restrict__ a, const float* __restrict__ b2,
                   const float* __restrict__ g, const float* __restrict__ beta,
                   float* __restrict__ out)
{
    const int row = blockIdx.x;
    const size_t off = (size_t)row * DD;
    const int t = threadIdx.x;
    __shared__ float r1[256], r2[256];

    float vloc[4];
    float s = 0.0f, s2 = 0.0f;
#pragma unroll
    for (int i = 0; i < 4; i++) {
        int d = t + i * 256;
        float vv = a[off + d] + b2[off + d];
        vloc[i] = vv;
        s += vv; s2 += vv * vv;
    }
    r1[t] = s; r2[t] = s2;
    __syncthreads();
    for (int o2 = 128; o2 > 0; o2 >>= 1) {
        if (t < o2) { r1[t] += r1[t + o2]; r2[t] += r2[t + o2]; }
        __syncthreads();
    }
    float mean = r1[0] * (1.0f / DD);
    float var  = r2[0] * (1.0f / DD) - mean * mean;
    float inv  = rsqrtf(var + 1e-5f);
#pragma unroll
    for (int i = 0; i < 4; i++) {
        int d = t + i * 256;
        out[off + d] = (vloc[i] - mean) * inv * g[d] + beta[d];
    }
}

// ---------------------------------------------------------------------------
// s = sigmoid(feat @ Ws + bs); one warp per token
// ---------------------------------------------------------------------------
__global__ __launch_bounds__(256)
void score_kernel(const float* __restrict__ feat, const float* __restrict__ Ws,
                  const float* __restrict__ bs, float* __restrict__ sbuf)
{
    int token = blockIdx.x * 8 + (threadIdx.x >> 5);
    int lane  = threadIdx.x & 31;
    const float* f = feat + (size_t)token * DD;
    float acc = 0.0f;
    for (int i = lane; i < DD; i += 32) acc += f[i] * Ws[i];
#pragma unroll
    for (int m = 16; m; m >>= 1) acc += __shfl_xor_sync(0xffffffffu, acc, m);
    if (lane == 0) sbuf[token] = 1.0f / (1.0f + expf(-(acc + bs[0])));
}

// ---------------------------------------------------------------------------
// Per-batch inclusive scan of sv, floor -> segment ids, max over valid
// ---------------------------------------------------------------------------
__global__ __launch_bounds__(1024)
void scan_kernel(const float* __restrict__ sbuf, const float* __restrict__ masks,
                 float* __restrict__ svbuf, int* __restrict__ segbuf,
                 float* __restrict__ maxseg)
{
    const int b = blockIdx.x;
    const int t = threadIdx.x;
    __shared__ float sc[SS];
    __shared__ float mr[SS];

    float valid = masks[b * SS + t];
    float sv = (valid > 0.0f) ? sbuf[b * SS + t] : 0.0f;
    svbuf[b * SS + t] = sv;
    sc[t] = sv;
    __syncthreads();
    for (int off = 1; off < SS; off <<= 1) {
        float vprev = (t >= off) ? sc[t - off] : 0.0f;
        __syncthreads();
        sc[t] += vprev;
        __syncthreads();
    }
    float c = floorf(sc[t]);
    int seg = (int)c;
    seg = seg < 0 ? 0 : (seg > SS - 1 ? SS - 1 : seg);
    segbuf[b * SS + t] = seg;

    mr[t] = (valid > 0.0f) ? c : -1.0f;
    __syncthreads();
    for (int off = 512; off > 0; off >>= 1) {
        if (t < off) mr[t] = fmaxf(mr[t], mr[t + off]);
        __syncthreads();
    }
    if (t == 0) maxseg[b] = mr[0];
}

// ---------------------------------------------------------------------------
// pooled[b,g,:] = sum_{s: seg[b,s]==g} x[b,s,:]*sv[b,s] -> split bf16 output
// ---------------------------------------------------------------------------
__global__ __launch_bounds__(256)
void pool_kernel(const float* __restrict__ x, const float* __restrict__ svbuf,
                 const int* __restrict__ segbuf,
                 __nv_bfloat16* __restrict__ ph, __nv_bfloat16* __restrict__ pl)
{
    const int g = blockIdx.x;
    const int b = blockIdx.y;
    const int* seg = segbuf + b * SS;

    int lo = 0, hi = SS;
    while (lo < hi) { int mid = (lo + hi) >> 1; if (seg[mid] < g) lo = mid + 1; else hi = mid; }
    int beg = lo;
    lo = beg; hi = SS;
    while (lo < hi) { int mid = (lo + hi) >> 1; if (seg[mid] < g + 1) lo = mid + 1; else hi = mid; }
    int end = lo;

    const int t = threadIdx.x;
    float acc[4] = {0.0f, 0.0f, 0.0f, 0.0f};
    for (int s = beg; s < end; s++) {
        float w = svbuf[b * SS + s];
        const float* xr = x + ((size_t)b * SS + s) * DD;
#pragma unroll
        for (int i = 0; i < 4; i++) acc[i] += xr[t + i * 256] * w;
    }
    size_t rbase = ((size_t)b * SS + g) * DD;
#pragma unroll
    for (int i = 0; i < 4; i++) {
        __nv_bfloat16 h, l;
        bsplit(acc[i], h, l);
        ph[rbase + t + i * 256] = h;
        pl[rbase + t + i * 256] = l;
    }
}

// ---------------------------------------------------------------------------
// new_mask[b,s] = (s <= max_seg[b]) ? 1 : 0
// ---------------------------------------------------------------------------
__global__ __launch_bounds__(1024)
void mask_kernel(const float* __restrict__ maxseg, float* __restrict__ outmask)
{
    const int b = blockIdx.x;
    const int t = threadIdx.x;
    outmask[b * SS + t] = ((float)t <= maxseg[b]) ? 1.0f : 0.0f;
}

// ---------------------------------------------------------------------------
// Host side
// ---------------------------------------------------------------------------
static void* sym_addr(const void* sym) {
    void* p = nullptr;
    cudaGetSymbolAddress(&p, sym);
    return p;
}

static void launch_tgemm(const float* A, const float* Bt, const float* bias,
                         float* C, int M, int N, int K, int act) {
    dim3 grid(N / 128, M / 128);
    mma_gemm_kernel<<<grid, 256>>>(A, Bt, bias, C, M, N, K, act);
}

static void launch_bgemm(const __nv_bfloat16* Ah, const __nv_bfloat16* Al,
                         const __nv_bfloat16* Bh, const __nv_bfloat16* Bl,
                         const float* bias, float* C,
                         __nv_bfloat16* Ch, __nv_bfloat16* Cl,
                         int M, int N, int K, int act, int out_split) {
    dim3 grid(N / 128, M / 128);
    bf16_gemm_kernel<<<grid, 256, BF_SMEM_BYTES>>>(Ah, Al, Bh, Bl, bias, C,
                                                   Ch, Cl, M, N, K, act, out_split);
}

static void launch_transpose(const float* W, float* Wt, int Kd, int Nd) {
    transpose_kernel<<<dim3(Nd / 32, Kd / 32), 256>>>(W, Wt, Kd, Nd);
}

extern "C" void kernel_launch(void* const* d_in, const int* in_sizes, int n_in,
                              void* d_out, int out_size)
{
    (void)in_sizes; (void)n_in;
    const float* x     = (const float*)d_in[0];
    const float* masks = (const float*)d_in[1];
    const float* Wq  = (const float*)d_in[2];
    const float* bq  = (const float*)d_in[3];
    const float* Wk  = (const float*)d_in[4];
    const float* bk  = (const float*)d_in[5];
    const float* Wv  = (const float*)d_in[6];
    const float* bv  = (const float*)d_in[7];
    const float* Wo  = (const float*)d_in[8];
    const float* bo  = (const float*)d_in[9];
    const float* g1  = (const float*)d_in[10];
    const float* be1 = (const float*)d_in[11];
    const float* g2  = (const float*)d_in[12];
    const float* be2 = (const float*)d_in[13];
    const float* W1  = (const float*)d_in[14];
    const float* bf1 = (const float*)d_in[15];
    const float* W2  = (const float*)d_in[16];
    const float* bf2 = (const float*)d_in[17];
    const float* Ws  = (const float*)d_in[18];
    const float* bs  = (const float*)d_in[19];
    const float* P1  = (const float*)d_in[20];
    const float* bp1 = (const float*)d_in[21];
    const float* P2  = (const float*)d_in[22];
    const float* bp2 = (const float*)d_in[23];

    float* out = (float*)d_out;
    (void)out_size;

    cudaFuncSetAttribute(attn_mma_kernel,
                         cudaFuncAttributeMaxDynamicSharedMemorySize,
                         ATT_SMEM_BYTES);
    cudaFuncSetAttribute(bf16_gemm_kernel,
                         cudaFuncAttributeMaxDynamicSharedMemorySize,
                         BF_SMEM_BYTES);

    float* qkvb  = (float*)sym_addr(g_qkv);
    float* attb  = (float*)sym_addr(g_att);
    float* ob    = (float*)sym_addr(g_o);
    float* hb    = (float*)sym_addr(g_h);
    float* featb = (float*)sym_addr(g_feat);
    float* feat2b= (float*)sym_addr(g_feat2);
    float* ffb   = (float*)sym_addr(g_ff);
    float* sb    = (float*)sym_addr(g_s);
    float* svb   = (float*)sym_addr(g_sv);
    int*   segb  = (int*)sym_addr(g_seg);
    float* msb   = (float*)sym_addr(g_maxseg);
    float* bqkvb = (float*)sym_addr(g_bqkv);

    float* Wqkvt = (float*)sym_addr(g_wt_qkv);
    float* Wot = (float*)sym_addr(g_wt_o);
    float* W1t = (float*)sym_addr(g_wt_1);
    float* W2t = (float*)sym_addr(g_wt_2);

    __nv_bfloat16* p1h = (__nv_bfloat16*)sym_addr(g_p1h);
    __nv_bfloat16* p1l = (__nv_bfloat16*)sym_addr(g_p1l);
    __nv_bfloat16* p2h = (__nv_bfloat16*)sym_addr(g_p2h);
    __nv_bfloat16* p2l = (__nv_bfloat16*)sym_addr(g_p2l);
    __nv_bfloat16* poolh = (__nv_bfloat16*)sym_addr(g_poolh);
    __nv_bfloat16* pooll = (__nv_bfloat16*)sym_addr(g_pooll);
    __nv_bfloat16* phh = (__nv_bfloat16*)sym_addr(g_phh);
    __nv_bfloat16* phl = (__nv_bfloat16*)sym_addr(g_phl);

    // ---- weight prep ----
    launch_transpose(Wq, Wqkvt,               DD, DD);
    launch_transpose(Wk, Wqkvt + DD * DD,     DD, DD);
    launch_transpose(Wv, Wqkvt + 2 * DD * DD, DD, DD);
    launch_transpose(Wo, Wot, DD, DD);
    launch_transpose(W1, W1t, DD, FF);
    launch_transpose(W2, W2t, FF, DD);
    trans_split_kernel<<<dim3(HID / 32, DD / 32), 256>>>(P1, p1h, p1l, DD, HID);
    trans_split_kernel<<<dim3(HID / 32, HID / 32), 256>>>(P2, p2h, p2l, HID, HID);
    concat_bias_kernel<<<(QKVN + 255) / 256, 256>>>(bq, bk, bv, bqkvb);

    // ---- encoder layer, applied twice (tf32 exact path) ----
    const float* enc_in = x;
    float* enc_out = featb;
    for (int pass = 0; pass < 2; pass++) {
        int mode = pass;
        launch_tgemm(enc_in, Wqkvt, bqkvb, qkvb, TOK, QKVN, DD, 0);
        attn_mma_kernel<<<dim3(SS / 64, BB * HH), 128, ATT_SMEM_BYTES>>>(
            qkvb, masks, mode, attb);
        launch_tgemm(attb, Wot, bo, ob, TOK, DD, DD, 0);
        add_ln_kernel<<<TOK, 256>>>(enc_in, ob, g1, be1, hb);
        launch_tgemm(hb, W1t, bf1, ffb, TOK, FF, DD, 1);   // GELU
        launch_tgemm(ffb, W2t, bf2, ob, TOK, DD, FF, 0);
        add_ln_kernel<<<TOK, 256>>>(hb, ob, g2, be2, enc_out);
        enc_in = featb;
        enc_out = feat2b;
    }

    // ---- importance scores, cumsum segmentation ----
    score_kernel<<<TOK / 8, 256>>>(feat2b, Ws, bs, sb);
    scan_kernel<<<BB, 1024>>>(sb, masks, svb, segb, msb);

    // ---- weighted segment-sum pooling of original x (split bf16 output) ----
    pool_kernel<<<dim3(SS, BB), 256>>>(x, svb, segb, poolh, pooll);

    // ---- projector on bf16-split tensor cores ----
    launch_bgemm(poolh, pooll, p1h, p1l, bp1, nullptr, phh, phl,
                 TOK, HID, DD, 1, 1);                    // GELU, split out
    launch_bgemm(phh, phl, p2h, p2l, bp2, out, nullptr, nullptr,
                 TOK, HID, HID, 0, 0);                   // fp32 out

    // ---- new_mask appended after the [B,S,HID] output ----
    mask_kernel<<<BB, 1024>>>(msb, out + (size_t)TOK * HID);
}